// round 1
// baseline (speedup 1.0000x reference)
#include <cuda_runtime.h>
#include <cstdint>
#include <cfloat>

// Problem constants (fixed by the dataset)
#define B   64
#define H   1024
#define V   32000
#define T   40
#define G4  4096
#define SOS 1

// GEMM tiling
#define BM 64
#define BN 128
#define BK 32

static_assert(V  % BN == 0, "");
static_assert(G4 % BN == 0, "");
static_assert(H  % BK == 0, "");

// ---------------- persistent device state (no allocations allowed) ----------
__device__ float g_h[B * H];
__device__ float g_c[B * H];
__device__ float g_x0[B * H];        // embed[SOS] broadcast to all batch rows
__device__ float g_gates[B * G4];
__device__ int   g_sym[B];

// ---------------- packed f32x2 helpers (sm_100+: FFMA2) ---------------------
__device__ __forceinline__ void fma2(unsigned long long& d,
                                     unsigned long long a,
                                     unsigned long long b) {
    asm("fma.rn.f32x2 %0, %1, %2, %0;" : "+l"(d) : "l"(a), "l"(b));
}
__device__ __forceinline__ unsigned long long dup2(float x) {
    unsigned long long r;
    unsigned xi = __float_as_uint(x);
    asm("mov.b64 %0, {%1, %1};" : "=l"(r) : "r"(xi));
    return r;
}
__device__ __forceinline__ float2 unpack2(unsigned long long v) {
    union { unsigned long long u; float2 f; } cv;
    cv.u = v;
    return cv.f;
}

// ---------------- init: state, x0, symbol[0] ---------------------------------
__global__ void init_kernel(const float* __restrict__ h0,
                            const float* __restrict__ c0,
                            const float* __restrict__ embed,
                            float* __restrict__ out, int mode) {
    int idx = blockIdx.x * blockDim.x + threadIdx.x;
    if (idx < B * H) {
        g_h[idx]  = h0[idx];
        g_c[idx]  = c0[idx];
        g_x0[idx] = embed[(size_t)SOS * H + (idx & (H - 1))];
    }
    if (idx < B) {
        g_sym[idx] = SOS;
        if (mode) out[(size_t)B * T * V + (size_t)idx * T + 0] = (float)SOS;
    }
}

__global__ void fill_zero(float* __restrict__ p, int n) {
    int i = blockIdx.x * blockDim.x + threadIdx.x;
    if (i < n) p[i] = 0.0f;
}

// ---------------- projection GEMM: out[m, t, n] = A[m,:]·W[n,:] + bias[n] ---
// A: [B,H] (g_x0 if useX0 else g_h), W: [V,H] row-major, out: [B,T,V]
__global__ __launch_bounds__(256)
void proj_kernel(int useX0,
                 const float* __restrict__ Wg,
                 const float* __restrict__ bias,
                 float* __restrict__ out, int t) {
    __shared__ __align__(16) float As[BK][BM + 4];
    __shared__ __align__(16) float Ws[BK][BN + 4];

    const int tid = threadIdx.x;
    const int tx = tid & 15, ty = tid >> 4;
    const int n0 = blockIdx.x * BN;

    const int am0 = tid >> 3;            // 0..31 (also W local row base)
    const int am1 = am0 + 32;
    const int k4  = (tid & 7) << 2;      // float offset within K-tile
    const int ks  = (tid & 7) << 2;      // smem k-row base for stores

    const float* Abase = useX0 ? g_x0 : g_h;
    const float* arow0 = Abase + (size_t)am0 * H;
    const float* arow1 = Abase + (size_t)am1 * H;
    const float* wrow0 = Wg + (size_t)(n0 + am0)      * H;
    const float* wrow1 = Wg + (size_t)(n0 + am0 + 32) * H;
    const float* wrow2 = Wg + (size_t)(n0 + am0 + 64) * H;
    const float* wrow3 = Wg + (size_t)(n0 + am0 + 96) * H;

    unsigned long long acc[4][4];
#pragma unroll
    for (int i = 0; i < 4; i++)
#pragma unroll
        for (int j = 0; j < 4; j++) acc[i][j] = 0ull;

    float4 aR0 = *(const float4*)(arow0 + k4);
    float4 aR1 = *(const float4*)(arow1 + k4);
    float4 wR0 = *(const float4*)(wrow0 + k4);
    float4 wR1 = *(const float4*)(wrow1 + k4);
    float4 wR2 = *(const float4*)(wrow2 + k4);
    float4 wR3 = *(const float4*)(wrow3 + k4);

    for (int kt = 0; kt < H; kt += BK) {
#pragma unroll
        for (int j = 0; j < 4; j++) {
            As[ks + j][am0]      = ((float*)&aR0)[j];
            As[ks + j][am1]      = ((float*)&aR1)[j];
            Ws[ks + j][am0]      = ((float*)&wR0)[j];
            Ws[ks + j][am0 + 32] = ((float*)&wR1)[j];
            Ws[ks + j][am0 + 64] = ((float*)&wR2)[j];
            Ws[ks + j][am0 + 96] = ((float*)&wR3)[j];
        }
        __syncthreads();

        if (kt + BK < H) {
            int ko = kt + BK + k4;
            aR0 = *(const float4*)(arow0 + ko);
            aR1 = *(const float4*)(arow1 + ko);
            wR0 = *(const float4*)(wrow0 + ko);
            wR1 = *(const float4*)(wrow1 + ko);
            wR2 = *(const float4*)(wrow2 + ko);
            wR3 = *(const float4*)(wrow3 + ko);
        }

#pragma unroll 16
        for (int k = 0; k < BK; k++) {
            float4 a = *(const float4*)&As[k][ty << 2];
            ulonglong2 w0 = *(const ulonglong2*)&Ws[k][tx << 2];
            ulonglong2 w1 = *(const ulonglong2*)&Ws[k][64 + (tx << 2)];
            unsigned long long ad;
            ad = dup2(a.x);
            fma2(acc[0][0], ad, w0.x); fma2(acc[0][1], ad, w0.y);
            fma2(acc[0][2], ad, w1.x); fma2(acc[0][3], ad, w1.y);
            ad = dup2(a.y);
            fma2(acc[1][0], ad, w0.x); fma2(acc[1][1], ad, w0.y);
            fma2(acc[1][2], ad, w1.x); fma2(acc[1][3], ad, w1.y);
            ad = dup2(a.z);
            fma2(acc[2][0], ad, w0.x); fma2(acc[2][1], ad, w0.y);
            fma2(acc[2][2], ad, w1.x); fma2(acc[2][3], ad, w1.y);
            ad = dup2(a.w);
            fma2(acc[3][0], ad, w0.x); fma2(acc[3][1], ad, w0.y);
            fma2(acc[3][2], ad, w1.x); fma2(acc[3][3], ad, w1.y);
        }
        __syncthreads();
    }

#pragma unroll
    for (int i = 0; i < 4; i++) {
        int m = (ty << 2) + i;
        float* orow = out + ((size_t)m * T + t) * (size_t)V + n0;
#pragma unroll
        for (int jp = 0; jp < 4; jp++) {
            int n = (jp < 2) ? ((tx << 2) + jp * 2)
                             : (64 + (tx << 2) + (jp - 2) * 2);
            float2 v = unpack2(acc[i][jp]);
            orow[n]     = v.x + bias[n0 + n];
            orow[n + 1] = v.y + bias[n0 + n + 1];
        }
    }
}

// ---------------- LSTM gates GEMM: gates = embed[sym]·w_ih^T + h·w_hh^T + b --
__global__ __launch_bounds__(256)
void lstm_gemm_kernel(const float* __restrict__ embed,
                      const float* __restrict__ w_ih,
                      const float* __restrict__ w_hh,
                      const float* __restrict__ b_ih,
                      const float* __restrict__ b_hh) {
    __shared__ __align__(16) float As[BK][BM + 4];
    __shared__ __align__(16) float Ws[BK][BN + 4];
    __shared__ int s_sym[B];

    const int tid = threadIdx.x;
    const int tx = tid & 15, ty = tid >> 4;
    const int n0 = blockIdx.x * BN;

    if (tid < B) s_sym[tid] = g_sym[tid];
    __syncthreads();

    const int am0 = tid >> 3;
    const int am1 = am0 + 32;
    const int k4  = (tid & 7) << 2;
    const int ks  = (tid & 7) << 2;

    unsigned long long acc[4][4];
#pragma unroll
    for (int i = 0; i < 4; i++)
#pragma unroll
        for (int j = 0; j < 4; j++) acc[i][j] = 0ull;

    for (int pass = 0; pass < 2; pass++) {
        const float* arow0;
        const float* arow1;
        const float* Wp;
        if (pass == 0) {
            arow0 = embed + (size_t)s_sym[am0] * H;
            arow1 = embed + (size_t)s_sym[am1] * H;
            Wp = w_ih;
        } else {
            arow0 = g_h + (size_t)am0 * H;
            arow1 = g_h + (size_t)am1 * H;
            Wp = w_hh;
        }
        const float* wrow0 = Wp + (size_t)(n0 + am0)      * H;
        const float* wrow1 = Wp + (size_t)(n0 + am0 + 32) * H;
        const float* wrow2 = Wp + (size_t)(n0 + am0 + 64) * H;
        const float* wrow3 = Wp + (size_t)(n0 + am0 + 96) * H;

        float4 aR0 = *(const float4*)(arow0 + k4);
        float4 aR1 = *(const float4*)(arow1 + k4);
        float4 wR0 = *(const float4*)(wrow0 + k4);
        float4 wR1 = *(const float4*)(wrow1 + k4);
        float4 wR2 = *(const float4*)(wrow2 + k4);
        float4 wR3 = *(const float4*)(wrow3 + k4);

        for (int kt = 0; kt < H; kt += BK) {
#pragma unroll
            for (int j = 0; j < 4; j++) {
                As[ks + j][am0]      = ((float*)&aR0)[j];
                As[ks + j][am1]      = ((float*)&aR1)[j];
                Ws[ks + j][am0]      = ((float*)&wR0)[j];
                Ws[ks + j][am0 + 32] = ((float*)&wR1)[j];
                Ws[ks + j][am0 + 64] = ((float*)&wR2)[j];
                Ws[ks + j][am0 + 96] = ((float*)&wR3)[j];
            }
            __syncthreads();

            if (kt + BK < H) {
                int ko = kt + BK + k4;
                aR0 = *(const float4*)(arow0 + ko);
                aR1 = *(const float4*)(arow1 + ko);
                wR0 = *(const float4*)(wrow0 + ko);
                wR1 = *(const float4*)(wrow1 + ko);
                wR2 = *(const float4*)(wrow2 + ko);
                wR3 = *(const float4*)(wrow3 + ko);
            }

#pragma unroll 16
            for (int k = 0; k < BK; k++) {
                float4 a = *(const float4*)&As[k][ty << 2];
                ulonglong2 w0 = *(const ulonglong2*)&Ws[k][tx << 2];
                ulonglong2 w1 = *(const ulonglong2*)&Ws[k][64 + (tx << 2)];
                unsigned long long ad;
                ad = dup2(a.x);
                fma2(acc[0][0], ad, w0.x); fma2(acc[0][1], ad, w0.y);
                fma2(acc[0][2], ad, w1.x); fma2(acc[0][3], ad, w1.y);
                ad = dup2(a.y);
                fma2(acc[1][0], ad, w0.x); fma2(acc[1][1], ad, w0.y);
                fma2(acc[1][2], ad, w1.x); fma2(acc[1][3], ad, w1.y);
                ad = dup2(a.z);
                fma2(acc[2][0], ad, w0.x); fma2(acc[2][1], ad, w0.y);
                fma2(acc[2][2], ad, w1.x); fma2(acc[2][3], ad, w1.y);
                ad = dup2(a.w);
                fma2(acc[3][0], ad, w0.x); fma2(acc[3][1], ad, w0.y);
                fma2(acc[3][2], ad, w1.x); fma2(acc[3][3], ad, w1.y);
            }
            __syncthreads();
        }
    }

#pragma unroll
    for (int i = 0; i < 4; i++) {
        int m = (ty << 2) + i;
        float* grow = g_gates + (size_t)m * G4 + n0;
#pragma unroll
        for (int jp = 0; jp < 4; jp++) {
            int n = (jp < 2) ? ((tx << 2) + jp * 2)
                             : (64 + (tx << 2) + (jp - 2) * 2);
            float2 v = unpack2(acc[i][jp]);
            grow[n]     = v.x + b_ih[n0 + n]     + b_hh[n0 + n];
            grow[n + 1] = v.y + b_ih[n0 + n + 1] + b_hh[n0 + n + 1];
        }
    }
}

// ---------------- LSTM nonlinearity: h,c update ------------------------------
__global__ void lstm_act_kernel() {
    int idx = blockIdx.x * blockDim.x + threadIdx.x;   // B*H threads
    int b = idx >> 10;
    int j = idx & (H - 1);
    const float* gr = g_gates + (size_t)b * G4;
    float gi = gr[j];
    float gf = gr[j + 1024];
    float gg = gr[j + 2048];
    float go = gr[j + 3072];
    float c  = g_c[idx];
    float si = 1.0f / (1.0f + expf(-gi));
    float sf = 1.0f / (1.0f + expf(-gf));
    float so = 1.0f / (1.0f + expf(-go));
    float c2 = sf * c + si * tanhf(gg);
    g_c[idx] = c2;
    g_h[idx] = so * tanhf(c2);
}

// ---------------- greedy argmax over logits row (first-index ties) -----------
__global__ void argmax_kernel(float* __restrict__ out, int t, int mode) {
    int b = blockIdx.x;
    const float* row = out + ((size_t)b * T + t) * (size_t)V;
    float best = -FLT_MAX;
    int bi = 0;
    for (int n = threadIdx.x; n < V; n += 256) {
        float v = row[n];
        if (v > best) { best = v; bi = n; }
    }
    __shared__ float sv[256];
    __shared__ int   si[256];
    sv[threadIdx.x] = best;
    si[threadIdx.x] = bi;
    __syncthreads();
    for (int s = 128; s > 0; s >>= 1) {
        if (threadIdx.x < s) {
            float ov = sv[threadIdx.x + s];
            int   oi = si[threadIdx.x + s];
            if (ov > sv[threadIdx.x] ||
                (ov == sv[threadIdx.x] && oi < si[threadIdx.x])) {
                sv[threadIdx.x] = ov;
                si[threadIdx.x] = oi;
            }
        }
        __syncthreads();
    }
    if (threadIdx.x == 0) {
        g_sym[b] = si[0];
        if (mode) out[(size_t)B * T * V + (size_t)b * T + t] = (float)si[0];
    }
}

// ---------------- launch -----------------------------------------------------
extern "C" void kernel_launch(void* const* d_in, const int* in_sizes, int n_in,
                              void* d_out, int out_size) {
    const float* h0    = (const float*)d_in[1];
    const float* c0    = (const float*)d_in[2];
    const float* embed = (const float*)d_in[5];
    const float* w_ih  = (const float*)d_in[6];
    const float* w_hh  = (const float*)d_in[7];
    const float* b_ih  = (const float*)d_in[8];
    const float* b_hh  = (const float*)d_in[9];
    const float* w_out = (const float*)d_in[10];
    const float* b_out = (const float*)d_in[11];
    float* out = (float*)d_out;

    const long long BTV = (long long)B * T * V;
    long long extra = (long long)out_size - BTV;
    int mode = (extra >= (long long)(B * T)) ? 1 : 0;

    init_kernel<<<(B * H + 511) / 512, 512>>>(h0, c0, embed, out, mode);

    // Zero any tail region we don't otherwise write (output buffer is poisoned)
    long long zstart = BTV + (mode ? (long long)(B * T) : 0);
    long long zcount = (long long)out_size - zstart;
    if (zcount > 0)
        fill_zero<<<(int)((zcount + 255) / 256), 256>>>(out + zstart, (int)zcount);

    // t = 0: dec_0 = embed[SOS] @ w_out^T + b_out   (no LSTM step)
    proj_kernel<<<V / BN, 256>>>(1, w_out, b_out, out, 0);

    // t = 1..T-1: LSTM step on embed[sym_{t-1}], project, argmax
    for (int t = 1; t < T; t++) {
        lstm_gemm_kernel<<<G4 / BN, 256>>>(embed, w_ih, w_hh, b_ih, b_hh);
        lstm_act_kernel<<<(B * H) / 256, 256>>>();
        proj_kernel<<<V / BN, 256>>>(0, w_out, b_out, out, t);
        argmax_kernel<<<B, 256>>>(out, t, mode);
    }
}

// round 7
// speedup vs baseline: 1.4634x; 1.4634x over previous
#include <cuda_runtime.h>
#include <cuda_bf16.h>
#include <mma.h>
#include <cstdint>
#include <cfloat>

using namespace nvcuda;

#define B   64
#define H   1024
#define V   32000
#define T   40
#define G4  4096
#define SOS 1

// ---------------- persistent device state (device-code access ONLY) ----------
__device__ float g_h[B * H];
__device__ float g_c[B * H];
__device__ float g_x0[B * H];        // embed[SOS] broadcast to all batch rows
__device__ float g_gates[B * G4];
__device__ int   g_sym[B];

// ---------------- bf16 split helpers ------------------------------------------
__device__ __forceinline__ uint32_t packbf(__nv_bfloat16 a, __nv_bfloat16 b) {
    __nv_bfloat162 v;
    v.x = a; v.y = b;
    uint32_t r;
    memcpy(&r, &v, 4);
    return r;
}
__device__ __forceinline__ void split2(float x, float y,
                                       uint32_t& hw, uint32_t& lw) {
    __nv_bfloat16 hx = __float2bfloat16_rn(x);
    __nv_bfloat16 hy = __float2bfloat16_rn(y);
    __nv_bfloat16 lx = __float2bfloat16_rn(x - __bfloat162float(hx));
    __nv_bfloat16 ly = __float2bfloat16_rn(y - __bfloat162float(hy));
    hw = packbf(hx, hy);
    lw = packbf(lx, ly);
}
__device__ __forceinline__ void cvt_store(uint32_t* hw, uint32_t* lw,
                                          float4 v0, float4 v1) {
    split2(v0.x, v0.y, hw[0], lw[0]);
    split2(v0.z, v0.w, hw[1], lw[1]);
    split2(v1.x, v1.y, hw[2], lw[2]);
    split2(v1.z, v1.w, hw[3], lw[3]);
}

#define PITCHE 40      // smem row pitch in bf16 elements (32 data + 8 pad)

// ---------------- HMMA projection via wmma ------------------------------------
// D[m, n] = sum_k W[m,k] * X[n,k]; X = g_x0 (useX0) or g_h; writes
// dst[(n*T + t)*V + m0+m] + bias[m].  3-term bf16 split: Wh*Xh + Wh*Xl + Wl*Xh.
__global__ __launch_bounds__(256)
void proj_wmma(const float* __restrict__ Wg, int useX0,
               float* __restrict__ dst, int t, const float* __restrict__ bias)
{
    __shared__ __align__(32) __nv_bfloat16 sAh[64 * PITCHE];
    __shared__ __align__(32) __nv_bfloat16 sAl[64 * PITCHE];
    __shared__ __align__(32) __nv_bfloat16 sBh[64 * PITCHE];
    __shared__ __align__(32) __nv_bfloat16 sBl[64 * PITCHE];
    __shared__ __align__(32) float sC[64 * 68];

    const float* Xs = useX0 ? g_x0 : g_h;   // device-side symbol resolution

    const int tid = threadIdx.x;
    const int wid = tid >> 5;
    const int ms = (wid & 3) * 16;     // m strip
    const int nb = (wid >> 2) * 32;    // n half
    const int m0 = blockIdx.x * 64;

    const int lrow = tid >> 2, lch = tid & 3;   // 64 rows x 4 loader threads
    const float* Arow = Wg + (size_t)(m0 + lrow) * H + lch * 8;
    const float* Brow = Xs + (size_t)lrow * H + lch * 8;
    const int wbase = lrow * (PITCHE / 2) + lch * 4;   // word index in smem

    uint32_t* wAh = reinterpret_cast<uint32_t*>(sAh);
    uint32_t* wAl = reinterpret_cast<uint32_t*>(sAl);
    uint32_t* wBh = reinterpret_cast<uint32_t*>(sBh);
    uint32_t* wBl = reinterpret_cast<uint32_t*>(sBl);

    wmma::fragment<wmma::accumulator, 16, 16, 16, float> fC[2];
    wmma::fill_fragment(fC[0], 0.0f);
    wmma::fill_fragment(fC[1], 0.0f);

    float4 ra0 = *(const float4*)(Arow);
    float4 ra1 = *(const float4*)(Arow + 4);
    float4 rb0 = *(const float4*)(Brow);
    float4 rb1 = *(const float4*)(Brow + 4);

    for (int kt = 0; kt < H; kt += 32) {
        cvt_store(wAh + wbase, wAl + wbase, ra0, ra1);
        cvt_store(wBh + wbase, wBl + wbase, rb0, rb1);
        __syncthreads();

        if (kt + 32 < H) {
            ra0 = *(const float4*)(Arow + kt + 32);
            ra1 = *(const float4*)(Arow + kt + 36);
            rb0 = *(const float4*)(Brow + kt + 32);
            rb1 = *(const float4*)(Brow + kt + 36);
        }

#pragma unroll
        for (int ks = 0; ks < 32; ks += 16) {
            wmma::fragment<wmma::matrix_a, 16, 16, 16, __nv_bfloat16,
                           wmma::row_major> fAh, fAl;
            wmma::load_matrix_sync(fAh, sAh + ms * PITCHE + ks, PITCHE);
            wmma::load_matrix_sync(fAl, sAl + ms * PITCHE + ks, PITCHE);
#pragma unroll
            for (int j = 0; j < 2; j++) {
                wmma::fragment<wmma::matrix_b, 16, 16, 16, __nv_bfloat16,
                               wmma::col_major> fBh, fBl;
                const int nr = nb + j * 16;
                wmma::load_matrix_sync(fBh, sBh + nr * PITCHE + ks, PITCHE);
                wmma::load_matrix_sync(fBl, sBl + nr * PITCHE + ks, PITCHE);
                wmma::mma_sync(fC[j], fAh, fBh, fC[j]);
                wmma::mma_sync(fC[j], fAh, fBl, fC[j]);
                wmma::mma_sync(fC[j], fAl, fBh, fC[j]);
            }
        }
        __syncthreads();
    }

    wmma::store_matrix_sync(sC + ms * 68 + nb,      fC[0], 68, wmma::mem_row_major);
    wmma::store_matrix_sync(sC + ms * 68 + nb + 16, fC[1], 68, wmma::mem_row_major);
    __syncthreads();

    const int ml = tid & 63;           // local m (vocab row)
    const int nlb = tid >> 6;          // 0..3
    const int gm = m0 + ml;
    const float bb = bias[gm];
#pragma unroll
    for (int r = 0; r < 16; r++) {
        const int n = nlb + r * 4;     // batch index
        dst[((size_t)n * T + t) * (size_t)V + gm] = sC[ml * 68 + n] + bb;
    }
}

// ---------------- HMMA LSTM gates via wmma ------------------------------------
// gates[n, m] = sum_k w_ih[m,k]*x[n,k] + w_hh[m,k]*h[n,k] + b_ih[m] + b_hh[m]
// x[n] = embed[g_sym[n]]; writes g_gates (device-direct).
__global__ __launch_bounds__(256)
void lstm_wmma(const float* __restrict__ embed,
               const float* __restrict__ w_ih, const float* __restrict__ w_hh,
               const float* __restrict__ b_ih, const float* __restrict__ b_hh)
{
    __shared__ __align__(32) __nv_bfloat16 sAh[64 * PITCHE];
    __shared__ __align__(32) __nv_bfloat16 sAl[64 * PITCHE];
    __shared__ __align__(32) __nv_bfloat16 sBh[64 * PITCHE];
    __shared__ __align__(32) __nv_bfloat16 sBl[64 * PITCHE];
    __shared__ __align__(32) float sC[64 * 68];
    __shared__ int s_sym[B];

    const int tid = threadIdx.x;
    const int wid = tid >> 5;
    const int ms = (wid & 3) * 16;
    const int nb = (wid >> 2) * 32;
    const int m0 = blockIdx.x * 64;

    if (tid < B) s_sym[tid] = g_sym[tid];
    __syncthreads();

    const int lrow = tid >> 2, lch = tid & 3;
    const int wbase = lrow * (PITCHE / 2) + lch * 4;

    uint32_t* wAh = reinterpret_cast<uint32_t*>(sAh);
    uint32_t* wAl = reinterpret_cast<uint32_t*>(sAl);
    uint32_t* wBh = reinterpret_cast<uint32_t*>(sBh);
    uint32_t* wBl = reinterpret_cast<uint32_t*>(sBl);

    wmma::fragment<wmma::accumulator, 16, 16, 16, float> fC[2];
    wmma::fill_fragment(fC[0], 0.0f);
    wmma::fill_fragment(fC[1], 0.0f);

    for (int pass = 0; pass < 2; pass++) {
        const float* Wg = pass ? w_hh : w_ih;
        const float* Arow = Wg + (size_t)(m0 + lrow) * H + lch * 8;
        const float* Brow = (pass ? (g_h + (size_t)lrow * H)
                                  : (embed + (size_t)s_sym[lrow] * H)) + lch * 8;

        float4 ra0 = *(const float4*)(Arow);
        float4 ra1 = *(const float4*)(Arow + 4);
        float4 rb0 = *(const float4*)(Brow);
        float4 rb1 = *(const float4*)(Brow + 4);

        for (int kt = 0; kt < H; kt += 32) {
            cvt_store(wAh + wbase, wAl + wbase, ra0, ra1);
            cvt_store(wBh + wbase, wBl + wbase, rb0, rb1);
            __syncthreads();

            if (kt + 32 < H) {
                ra0 = *(const float4*)(Arow + kt + 32);
                ra1 = *(const float4*)(Arow + kt + 36);
                rb0 = *(const float4*)(Brow + kt + 32);
                rb1 = *(const float4*)(Brow + kt + 36);
            }

#pragma unroll
            for (int ks = 0; ks < 32; ks += 16) {
                wmma::fragment<wmma::matrix_a, 16, 16, 16, __nv_bfloat16,
                               wmma::row_major> fAh, fAl;
                wmma::load_matrix_sync(fAh, sAh + ms * PITCHE + ks, PITCHE);
                wmma::load_matrix_sync(fAl, sAl + ms * PITCHE + ks, PITCHE);
#pragma unroll
                for (int j = 0; j < 2; j++) {
                    wmma::fragment<wmma::matrix_b, 16, 16, 16, __nv_bfloat16,
                                   wmma::col_major> fBh, fBl;
                    const int nr = nb + j * 16;
                    wmma::load_matrix_sync(fBh, sBh + nr * PITCHE + ks, PITCHE);
                    wmma::load_matrix_sync(fBl, sBl + nr * PITCHE + ks, PITCHE);
                    wmma::mma_sync(fC[j], fAh, fBh, fC[j]);
                    wmma::mma_sync(fC[j], fAh, fBl, fC[j]);
                    wmma::mma_sync(fC[j], fAl, fBh, fC[j]);
                }
            }
            __syncthreads();
        }
    }

    wmma::store_matrix_sync(sC + ms * 68 + nb,      fC[0], 68, wmma::mem_row_major);
    wmma::store_matrix_sync(sC + ms * 68 + nb + 16, fC[1], 68, wmma::mem_row_major);
    __syncthreads();

    const int ml = tid & 63;
    const int nlb = tid >> 6;
    const int gm = m0 + ml;
    const float bb = b_ih[gm] + b_hh[gm];
#pragma unroll
    for (int r = 0; r < 16; r++) {
        const int n = nlb + r * 4;
        g_gates[(size_t)n * G4 + gm] = sC[ml * 68 + n] + bb;
    }
}

// ---------------- small kernels (round-1 verbatim) ----------------------------
__global__ void init_kernel(const float* __restrict__ h0,
                            const float* __restrict__ c0,
                            const float* __restrict__ embed,
                            float* __restrict__ out, int mode) {
    int idx = blockIdx.x * blockDim.x + threadIdx.x;
    if (idx < B * H) {
        g_h[idx]  = h0[idx];
        g_c[idx]  = c0[idx];
        g_x0[idx] = embed[(size_t)SOS * H + (idx & (H - 1))];
    }
    if (idx < B) {
        g_sym[idx] = SOS;
        if (mode) out[(size_t)B * T * V + (size_t)idx * T + 0] = (float)SOS;
    }
}

__global__ void fill_zero(float* __restrict__ p, int n) {
    int i = blockIdx.x * blockDim.x + threadIdx.x;
    if (i < n) p[i] = 0.0f;
}

__global__ void lstm_act_kernel() {
    int idx = blockIdx.x * blockDim.x + threadIdx.x;   // B*H threads
    int b = idx >> 10;
    int j = idx & (H - 1);
    const float* gr = g_gates + (size_t)b * G4;
    float gi = gr[j];
    float gf = gr[j + 1024];
    float gg = gr[j + 2048];
    float go = gr[j + 3072];
    float c  = g_c[idx];
    float si = 1.0f / (1.0f + expf(-gi));
    float sf = 1.0f / (1.0f + expf(-gf));
    float so = 1.0f / (1.0f + expf(-go));
    float c2 = sf * c + si * tanhf(gg);
    g_c[idx] = c2;
    g_h[idx] = so * tanhf(c2);
}

__global__ void argmax_kernel(float* __restrict__ out, int t, int mode) {
    int b = blockIdx.x;
    const float* row = out + ((size_t)b * T + t) * (size_t)V;
    float best = -FLT_MAX;
    int bi = 0;
    for (int n = threadIdx.x; n < V; n += 256) {
        float v = row[n];
        if (v > best) { best = v; bi = n; }
    }
    __shared__ float sv[256];
    __shared__ int   si[256];
    sv[threadIdx.x] = best;
    si[threadIdx.x] = bi;
    __syncthreads();
    for (int s = 128; s > 0; s >>= 1) {
        if (threadIdx.x < s) {
            float ov = sv[threadIdx.x + s];
            int   oi = si[threadIdx.x + s];
            if (ov > sv[threadIdx.x] ||
                (ov == sv[threadIdx.x] && oi < si[threadIdx.x])) {
                sv[threadIdx.x] = ov;
                si[threadIdx.x] = oi;
            }
        }
        __syncthreads();
    }
    if (threadIdx.x == 0) {
        g_sym[b] = si[0];
        if (mode) out[(size_t)B * T * V + (size_t)b * T + t] = (float)si[0];
    }
}

// ---------------- launch -----------------------------------------------------
extern "C" void kernel_launch(void* const* d_in, const int* in_sizes, int n_in,
                              void* d_out, int out_size) {
    const float* h0    = (const float*)d_in[1];
    const float* c0    = (const float*)d_in[2];
    const float* embed = (const float*)d_in[5];
    const float* w_ih  = (const float*)d_in[6];
    const float* w_hh  = (const float*)d_in[7];
    const float* b_ih  = (const float*)d_in[8];
    const float* b_hh  = (const float*)d_in[9];
    const float* w_out = (const float*)d_in[10];
    const float* b_out = (const float*)d_in[11];
    float* out = (float*)d_out;

    const long long BTV = (long long)B * T * V;
    long long extra = (long long)out_size - BTV;
    int mode = (extra >= (long long)(B * T)) ? 1 : 0;

    init_kernel<<<(B * H + 511) / 512, 512>>>(h0, c0, embed, out, mode);

    long long zstart = BTV + (mode ? (long long)(B * T) : 0);
    long long zcount = (long long)out_size - zstart;
    if (zcount > 0)
        fill_zero<<<(int)((zcount + 255) / 256), 256>>>(out + zstart, (int)zcount);

    // t = 0: dec_0 = embed[SOS] @ w_out^T + b_out
    proj_wmma<<<V / 64, 256>>>(w_out, 1, out, 0, b_out);

    // t = 1..T-1
    for (int t = 1; t < T; t++) {
        lstm_wmma<<<G4 / 64, 256>>>(embed, w_ih, w_hh, b_ih, b_hh);
        lstm_act_kernel<<<(B * H) / 256, 256>>>();
        proj_wmma<<<V / 64, 256>>>(w_out, 0, out, t, b_out);
        argmax_kernel<<<B, 256>>>(out, t, mode);
    }
}

// round 8
// speedup vs baseline: 2.7273x; 1.8637x over previous
#include <cuda_runtime.h>
#include <cuda_bf16.h>
#include <mma.h>
#include <cstdint>
#include <cfloat>

using namespace nvcuda;

#define B   64
#define H   1024
#define V   32000
#define T   40
#define G4  4096
#define SOS 1

// GEMM geometry: 64 weight rows x 64 batch x K-chunk 64, 16 stages over H
#define KC   64
#define PE   72                    // smem pitch in bf16 elements (64 + 8 pad)
#define ROWB 144                   // pitch bytes
#define ARRB (64 * ROWB)           // 9216 bytes per operand array
#define STAGEB (4 * ARRB)          // 36864 per stage
#define DSMEM (2 * STAGEB)         // 73728 dynamic smem
#define NST  (H / KC)              // 16 stages

// ---------------- persistent device state (device-code access ONLY) ----------
__device__ __align__(16) __nv_bfloat16 g_Wout_h[(size_t)V * H];
__device__ __align__(16) __nv_bfloat16 g_Wout_l[(size_t)V * H];
__device__ __align__(16) __nv_bfloat16 g_Wih_h[(size_t)G4 * H];
__device__ __align__(16) __nv_bfloat16 g_Wih_l[(size_t)G4 * H];
__device__ __align__(16) __nv_bfloat16 g_Whh_h[(size_t)G4 * H];
__device__ __align__(16) __nv_bfloat16 g_Whh_l[(size_t)G4 * H];
__device__ __align__(16) __nv_bfloat16 g_x0h[B * H], g_x0l[B * H];
__device__ __align__(16) __nv_bfloat16 g_xh[B * H],  g_xl[B * H];
__device__ __align__(16) __nv_bfloat16 g_hh[B * H],  g_hl[B * H];
__device__ float g_c[B * H];
__device__ float g_gp0[B * G4];    // w_ih * x partial
__device__ float g_gp1[B * G4];    // w_hh * h partial
__device__ int   g_sym[B];

// ---------------- helpers ------------------------------------------------------
__device__ __forceinline__ uint32_t smem_u32(const void* p) {
    uint32_t a;
    asm("{ .reg .u64 t; cvta.to.shared.u64 t, %1; cvt.u32.u64 %0, t; }"
        : "=r"(a) : "l"(p));
    return a;
}
__device__ __forceinline__ void cp16(uint32_t s, const void* g) {
    asm volatile("cp.async.cg.shared.global [%0], [%1], 16;" :: "r"(s), "l"(g));
}
__device__ __forceinline__ void cp_commit() {
    asm volatile("cp.async.commit_group;" ::: "memory");
}
__device__ __forceinline__ void cp_wait1() {
    asm volatile("cp.async.wait_group 1;" ::: "memory");
}
__device__ __forceinline__ void cp_wait0() {
    asm volatile("cp.async.wait_group 0;" ::: "memory");
}
__device__ __forceinline__ void split_pair(float x, __nv_bfloat16& hi, __nv_bfloat16& lo) {
    hi = __float2bfloat16_rn(x);
    lo = __float2bfloat16_rn(x - __bfloat162float(hi));
}

// ---------------- shared GEMM mainloop -----------------------------------------
// Computes D[64 m-rows x 64 n-cols] = sum_k A[m0+m, k] * Bt[n, k] over K=H with
// the 3-term bf16 split (Ah*Bh + Ah*Bl + Al*Bh). Result staged into sC (pitch 68).
__device__ __forceinline__ void gemm64(
    const __nv_bfloat16* __restrict__ Ah, const __nv_bfloat16* __restrict__ Al,
    const __nv_bfloat16* __restrict__ Bh, const __nv_bfloat16* __restrict__ Bl,
    int m0, char* sm, float* sC)
{
    const int tid = threadIdx.x;
    const int wid = tid >> 5;
    const int ms = (wid & 3) * 16;
    const int nb = (wid >> 2) * 32;
    const uint32_t sbase = smem_u32(sm);

    // loader mapping: 2 (row,c) pairs per thread, 4 arrays each
    const int r0 = tid >> 3,        c0 = tid & 7;
    const int r1 = (tid + 256) >> 3, c1 = tid & 7;
    const uint32_t so0 = (uint32_t)(r0 * ROWB + c0 * 16);
    const uint32_t so1 = (uint32_t)(r1 * ROWB + c1 * 16);

    wmma::fragment<wmma::accumulator, 16, 16, 16, float> fC[2];
    wmma::fill_fragment(fC[0], 0.0f);
    wmma::fill_fragment(fC[1], 0.0f);

    // prologue: 2 stages in flight
#pragma unroll
    for (int s = 0; s < 2; s++) {
        const int kt = s * KC;
        const uint32_t sb = sbase + (uint32_t)s * STAGEB;
        const size_t ga0 = (size_t)(m0 + r0) * H + kt + c0 * 8;
        const size_t ga1 = (size_t)(m0 + r1) * H + kt + c1 * 8;
        const size_t gb0 = (size_t)r0 * H + kt + c0 * 8;
        const size_t gb1 = (size_t)r1 * H + kt + c1 * 8;
        cp16(sb + 0 * ARRB + so0, Ah + ga0);  cp16(sb + 0 * ARRB + so1, Ah + ga1);
        cp16(sb + 1 * ARRB + so0, Al + ga0);  cp16(sb + 1 * ARRB + so1, Al + ga1);
        cp16(sb + 2 * ARRB + so0, Bh + gb0);  cp16(sb + 2 * ARRB + so1, Bh + gb1);
        cp16(sb + 3 * ARRB + so0, Bl + gb0);  cp16(sb + 3 * ARRB + so1, Bl + gb1);
        cp_commit();
    }

    for (int s = 0; s < NST; s++) {
        if (s < NST - 1) cp_wait1(); else cp_wait0();
        __syncthreads();

        const __nv_bfloat16* st =
            reinterpret_cast<const __nv_bfloat16*>(sm + (size_t)(s & 1) * STAGEB);
        const __nv_bfloat16* sAh = st;
        const __nv_bfloat16* sAl = st + ARRB / 2;
        const __nv_bfloat16* sBh = st + 2 * (ARRB / 2);
        const __nv_bfloat16* sBl = st + 3 * (ARRB / 2);

#pragma unroll
        for (int ks = 0; ks < KC; ks += 16) {
            wmma::fragment<wmma::matrix_a, 16, 16, 16, __nv_bfloat16,
                           wmma::row_major> fAh, fAl;
            wmma::load_matrix_sync(fAh, sAh + ms * PE + ks, PE);
            wmma::load_matrix_sync(fAl, sAl + ms * PE + ks, PE);
#pragma unroll
            for (int j = 0; j < 2; j++) {
                wmma::fragment<wmma::matrix_b, 16, 16, 16, __nv_bfloat16,
                               wmma::col_major> fBh, fBl;
                const int nr = nb + j * 16;
                wmma::load_matrix_sync(fBh, sBh + nr * PE + ks, PE);
                wmma::load_matrix_sync(fBl, sBl + nr * PE + ks, PE);
                wmma::mma_sync(fC[j], fAh, fBh, fC[j]);
                wmma::mma_sync(fC[j], fAh, fBl, fC[j]);
                wmma::mma_sync(fC[j], fAl, fBh, fC[j]);
            }
        }
        __syncthreads();

        if (s + 2 < NST) {
            const int kt = (s + 2) * KC;
            const uint32_t sb = sbase + (uint32_t)(s & 1) * STAGEB;
            const size_t ga0 = (size_t)(m0 + r0) * H + kt + c0 * 8;
            const size_t ga1 = (size_t)(m0 + r1) * H + kt + c1 * 8;
            const size_t gb0 = (size_t)r0 * H + kt + c0 * 8;
            const size_t gb1 = (size_t)r1 * H + kt + c1 * 8;
            cp16(sb + 0 * ARRB + so0, Ah + ga0);  cp16(sb + 0 * ARRB + so1, Ah + ga1);
            cp16(sb + 1 * ARRB + so0, Al + ga0);  cp16(sb + 1 * ARRB + so1, Al + ga1);
            cp16(sb + 2 * ARRB + so0, Bh + gb0);  cp16(sb + 2 * ARRB + so1, Bh + gb1);
            cp16(sb + 3 * ARRB + so0, Bl + gb0);  cp16(sb + 3 * ARRB + so1, Bl + gb1);
            cp_commit();
        }
    }

    // stage accumulators through smem (sC aliases stage 0; all loads complete)
    wmma::store_matrix_sync(sC + ms * 68 + nb,      fC[0], 68, wmma::mem_row_major);
    wmma::store_matrix_sync(sC + ms * 68 + nb + 16, fC[1], 68, wmma::mem_row_major);
    __syncthreads();
}

// ---------------- projection kernel --------------------------------------------
__global__ __launch_bounds__(256)
void proj_tc(int useX0, float* __restrict__ dst, int t,
             const float* __restrict__ bias)
{
    extern __shared__ char sm[];
    float* sC = reinterpret_cast<float*>(sm);
    const int m0 = blockIdx.x * 64;

    const __nv_bfloat16* Bh = useX0 ? g_x0h : g_hh;
    const __nv_bfloat16* Bl = useX0 ? g_x0l : g_hl;
    gemm64(g_Wout_h + (size_t)0, g_Wout_l + (size_t)0, Bh, Bl, m0, sm, sC);

    const int ml = threadIdx.x & 63;
    const int nlb = threadIdx.x >> 6;
    const int gm = m0 + ml;
    const float bb = bias[gm];
#pragma unroll
    for (int r = 0; r < 16; r++) {
        const int n = nlb + r * 4;
        dst[((size_t)n * T + t) * (size_t)V + gm] = sC[ml * 68 + n] + bb;
    }
}

// ---------------- LSTM gates kernel (pass-parallel) ----------------------------
__global__ __launch_bounds__(256)
void lstm_tc()
{
    extern __shared__ char sm[];
    float* sC = reinterpret_cast<float*>(sm);
    const int pass = blockIdx.x >> 6;
    const int m0 = (blockIdx.x & 63) * 64;

    const __nv_bfloat16* Ah = pass ? g_Whh_h : g_Wih_h;
    const __nv_bfloat16* Al = pass ? g_Whh_l : g_Wih_l;
    const __nv_bfloat16* Bh = pass ? g_hh : g_xh;
    const __nv_bfloat16* Bl = pass ? g_hl : g_xl;
    gemm64(Ah, Al, Bh, Bl, m0, sm, sC);

    float* gp = pass ? g_gp1 : g_gp0;
    const int ml = threadIdx.x & 63;
    const int nlb = threadIdx.x >> 6;
    const int gm = m0 + ml;
#pragma unroll
    for (int r = 0; r < 16; r++) {
        const int n = nlb + r * 4;
        gp[(size_t)n * G4 + gm] = sC[ml * 68 + n];
    }
}

// ---------------- weight pre-split (runs once per launch) ----------------------
__global__ void split_weights(const float* __restrict__ src, int which, int n4) {
    int i4 = blockIdx.x * blockDim.x + threadIdx.x;
    if (i4 >= n4) return;
    __nv_bfloat16* dh;
    __nv_bfloat16* dl;
    if (which == 0)      { dh = g_Wout_h; dl = g_Wout_l; }
    else if (which == 1) { dh = g_Wih_h;  dl = g_Wih_l; }
    else                 { dh = g_Whh_h;  dl = g_Whh_l; }
    float4 v = reinterpret_cast<const float4*>(src)[i4];
    __nv_bfloat16 h0, l0, h1, l1, h2, l2, h3, l3;
    split_pair(v.x, h0, l0);
    split_pair(v.y, h1, l1);
    split_pair(v.z, h2, l2);
    split_pair(v.w, h3, l3);
    size_t o = (size_t)i4 * 4;
    dh[o] = h0; dh[o + 1] = h1; dh[o + 2] = h2; dh[o + 3] = h3;
    dl[o] = l0; dl[o + 1] = l1; dl[o + 2] = l2; dl[o + 3] = l3;
}

// ---------------- small kernels -------------------------------------------------
__global__ void init_kernel(const float* __restrict__ h0,
                            const float* __restrict__ c0,
                            const float* __restrict__ embed,
                            float* __restrict__ out, int mode) {
    int idx = blockIdx.x * blockDim.x + threadIdx.x;
    if (idx < B * H) {
        g_c[idx] = c0[idx];
        __nv_bfloat16 hi, lo;
        split_pair(h0[idx], hi, lo);
        g_hh[idx] = hi;
        g_hl[idx] = lo;
        split_pair(embed[(size_t)SOS * H + (idx & (H - 1))], hi, lo);
        g_x0h[idx] = hi;
        g_x0l[idx] = lo;
    }
    if (idx < B) {
        g_sym[idx] = SOS;
        if (mode) out[(size_t)B * T * V + (size_t)idx * T + 0] = (float)SOS;
    }
}

__global__ void fill_zero(float* __restrict__ p, int n) {
    int i = blockIdx.x * blockDim.x + threadIdx.x;
    if (i < n) p[i] = 0.0f;
}

__global__ void gather_split_kernel(const float* __restrict__ embed) {
    int idx = blockIdx.x * blockDim.x + threadIdx.x;  // B*H
    int b = idx >> 10;
    int j = idx & (H - 1);
    __nv_bfloat16 hi, lo;
    split_pair(embed[(size_t)g_sym[b] * H + j], hi, lo);
    g_xh[idx] = hi;
    g_xl[idx] = lo;
}

__global__ void lstm_act_kernel(const float* __restrict__ b_ih,
                                const float* __restrict__ b_hh) {
    int idx = blockIdx.x * blockDim.x + threadIdx.x;   // B*H
    int b = idx >> 10;
    int j = idx & (H - 1);
    const size_t base = (size_t)b * G4;
    float gi = g_gp0[base + j]        + g_gp1[base + j]        + b_ih[j]        + b_hh[j];
    float gf = g_gp0[base + j + 1024] + g_gp1[base + j + 1024] + b_ih[j + 1024] + b_hh[j + 1024];
    float gg = g_gp0[base + j + 2048] + g_gp1[base + j + 2048] + b_ih[j + 2048] + b_hh[j + 2048];
    float go = g_gp0[base + j + 3072] + g_gp1[base + j + 3072] + b_ih[j + 3072] + b_hh[j + 3072];
    float c  = g_c[idx];
    float si = 1.0f / (1.0f + expf(-gi));
    float sf = 1.0f / (1.0f + expf(-gf));
    float so = 1.0f / (1.0f + expf(-go));
    float c2 = sf * c + si * tanhf(gg);
    float h2 = so * tanhf(c2);
    g_c[idx] = c2;
    __nv_bfloat16 hi, lo;
    split_pair(h2, hi, lo);
    g_hh[idx] = hi;
    g_hl[idx] = lo;
}

__global__ void argmax_kernel(float* __restrict__ out, int t, int mode) {
    int b = blockIdx.x;
    const float4* row4 = reinterpret_cast<const float4*>(
        out + ((size_t)b * T + t) * (size_t)V);
    float best = -FLT_MAX;
    int bi = 0;
    for (int n4 = threadIdx.x; n4 < V / 4; n4 += 256) {
        float4 v = row4[n4];
        int n = n4 * 4;
        if (v.x > best) { best = v.x; bi = n; }
        if (v.y > best) { best = v.y; bi = n + 1; }
        if (v.z > best) { best = v.z; bi = n + 2; }
        if (v.w > best) { best = v.w; bi = n + 3; }
    }
    __shared__ float sv[256];
    __shared__ int   si[256];
    sv[threadIdx.x] = best;
    si[threadIdx.x] = bi;
    __syncthreads();
    for (int s = 128; s > 0; s >>= 1) {
        if (threadIdx.x < s) {
            float ov = sv[threadIdx.x + s];
            int   oi = si[threadIdx.x + s];
            if (ov > sv[threadIdx.x] ||
                (ov == sv[threadIdx.x] && oi < si[threadIdx.x])) {
                sv[threadIdx.x] = ov;
                si[threadIdx.x] = oi;
            }
        }
        __syncthreads();
    }
    if (threadIdx.x == 0) {
        g_sym[b] = si[0];
        if (mode) out[(size_t)B * T * V + (size_t)b * T + t] = (float)si[0];
    }
}

// ---------------- launch ---------------------------------------------------------
extern "C" void kernel_launch(void* const* d_in, const int* in_sizes, int n_in,
                              void* d_out, int out_size) {
    const float* h0    = (const float*)d_in[1];
    const float* c0    = (const float*)d_in[2];
    const float* embed = (const float*)d_in[5];
    const float* w_ih  = (const float*)d_in[6];
    const float* w_hh  = (const float*)d_in[7];
    const float* b_ih  = (const float*)d_in[8];
    const float* b_hh  = (const float*)d_in[9];
    const float* w_out = (const float*)d_in[10];
    const float* b_out = (const float*)d_in[11];
    float* out = (float*)d_out;

    static int attr_done = 0;
    if (!attr_done) {
        cudaFuncSetAttribute(proj_tc, cudaFuncAttributeMaxDynamicSharedMemorySize, DSMEM);
        cudaFuncSetAttribute(lstm_tc, cudaFuncAttributeMaxDynamicSharedMemorySize, DSMEM);
        attr_done = 1;
    }

    const long long BTV = (long long)B * T * V;
    long long extra = (long long)out_size - BTV;
    int mode = (extra >= (long long)(B * T)) ? 1 : 0;

    init_kernel<<<(B * H + 511) / 512, 512>>>(h0, c0, embed, out, mode);

    // one-time bf16-pair weight splits
    split_weights<<<(V * H / 4 + 255) / 256, 256>>>(w_out, 0, V * H / 4);
    split_weights<<<(G4 * H / 4 + 255) / 256, 256>>>(w_ih, 1, G4 * H / 4);
    split_weights<<<(G4 * H / 4 + 255) / 256, 256>>>(w_hh, 2, G4 * H / 4);

    long long zstart = BTV + (mode ? (long long)(B * T) : 0);
    long long zcount = (long long)out_size - zstart;
    if (zcount > 0)
        fill_zero<<<(int)((zcount + 255) / 256), 256>>>(out + zstart, (int)zcount);

    // t = 0: dec_0 = embed[SOS] @ w_out^T + b_out
    proj_tc<<<V / 64, 256, DSMEM>>>(1, out, 0, b_out);

    // t = 1..T-1
    for (int t = 1; t < T; t++) {
        gather_split_kernel<<<(B * H) / 256, 256>>>(embed);
        lstm_tc<<<128, 256, DSMEM>>>();
        lstm_act_kernel<<<(B * H) / 256, 256>>>(b_ih, b_hh);
        proj_tc<<<V / 64, 256, DSMEM>>>(0, out, t, b_out);
        argmax_kernel<<<B, 256>>>(out, t, mode);
    }
}

// round 9
// speedup vs baseline: 3.0462x; 1.1169x over previous
#include <cuda_runtime.h>
#include <cuda_bf16.h>
#include <mma.h>
#include <cstdint>
#include <cfloat>

using namespace nvcuda;

#define B   64
#define H   1024
#define V   32000
#define T   40
#define G4  4096
#define SOS 1

#define KC   64
#define PE   72                     // smem pitch in bf16 elements
#define ROWB 144                    // pitch bytes
#define NST  (H / KC)               // 16 stages

// ---- LSTM geometry (BM=64) ----
#define ARRB64 (64 * ROWB)          // 9216
#define STG64  (4 * ARRB64)         // 36864
#define DSMEM_L (2 * STG64)         // 73728

// ---- proj geometry (BM=128) ----
#define ARRB128 (128 * ROWB)        // 18432
#define STG128  (2 * ARRB128 + 2 * ARRB64)   // 55296
#define DSMEM_P (2 * STG128)        // 110592

// ---------------- persistent device state (device-code access ONLY) ----------
__device__ __align__(16) __nv_bfloat16 g_Wout_h[(size_t)V * H];
__device__ __align__(16) __nv_bfloat16 g_Wout_l[(size_t)V * H];
__device__ __align__(16) __nv_bfloat16 g_Wih_h[(size_t)G4 * H];
__device__ __align__(16) __nv_bfloat16 g_Wih_l[(size_t)G4 * H];
__device__ __align__(16) __nv_bfloat16 g_Whh_h[(size_t)G4 * H];
__device__ __align__(16) __nv_bfloat16 g_Whh_l[(size_t)G4 * H];
__device__ __align__(16) __nv_bfloat16 g_xh[B * H],  g_xl[B * H];
__device__ __align__(16) __nv_bfloat16 g_hh[B * H],  g_hl[B * H];
__device__ float g_c[B * H];
__device__ float g_gp0[B * G4];
__device__ float g_gp1[B * G4];
__device__ int   g_sym[B];

// ---------------- helpers ------------------------------------------------------
__device__ __forceinline__ uint32_t smem_u32(const void* p) {
    uint32_t a;
    asm("{ .reg .u64 t; cvta.to.shared.u64 t, %1; cvt.u32.u64 %0, t; }"
        : "=r"(a) : "l"(p));
    return a;
}
__device__ __forceinline__ void cp16(uint32_t s, const void* g) {
    asm volatile("cp.async.cg.shared.global [%0], [%1], 16;" :: "r"(s), "l"(g));
}
__device__ __forceinline__ void cp_commit() {
    asm volatile("cp.async.commit_group;" ::: "memory");
}
__device__ __forceinline__ void cp_wait1() {
    asm volatile("cp.async.wait_group 1;" ::: "memory");
}
__device__ __forceinline__ void cp_wait0() {
    asm volatile("cp.async.wait_group 0;" ::: "memory");
}
__device__ __forceinline__ void split_pair(float x, __nv_bfloat16& hi, __nv_bfloat16& lo) {
    hi = __float2bfloat16_rn(x);
    lo = __float2bfloat16_rn(x - __bfloat162float(hi));
}

// ---------------- LSTM GEMM mainloop (BM=64; proven) ---------------------------
__device__ __forceinline__ void gemm64(
    const __nv_bfloat16* __restrict__ Ah, const __nv_bfloat16* __restrict__ Al,
    const __nv_bfloat16* __restrict__ Bh, const __nv_bfloat16* __restrict__ Bl,
    int m0, char* sm, float* sC)
{
    const int tid = threadIdx.x;
    const int wid = tid >> 5;
    const int ms = (wid & 3) * 16;
    const int nb = (wid >> 2) * 32;
    const uint32_t sbase = smem_u32(sm);

    const int r0 = tid >> 3,         c0 = tid & 7;
    const int r1 = (tid + 256) >> 3, c1 = tid & 7;
    const uint32_t so0 = (uint32_t)(r0 * ROWB + c0 * 16);
    const uint32_t so1 = (uint32_t)(r1 * ROWB + c1 * 16);

    wmma::fragment<wmma::accumulator, 16, 16, 16, float> fC[2];
    wmma::fill_fragment(fC[0], 0.0f);
    wmma::fill_fragment(fC[1], 0.0f);

#pragma unroll
    for (int s = 0; s < 2; s++) {
        const int kt = s * KC;
        const uint32_t sb = sbase + (uint32_t)s * STG64;
        const size_t ga0 = (size_t)(m0 + r0) * H + kt + c0 * 8;
        const size_t ga1 = (size_t)(m0 + r1) * H + kt + c1 * 8;
        const size_t gb0 = (size_t)r0 * H + kt + c0 * 8;
        const size_t gb1 = (size_t)r1 * H + kt + c1 * 8;
        cp16(sb + 0 * ARRB64 + so0, Ah + ga0);  cp16(sb + 0 * ARRB64 + so1, Ah + ga1);
        cp16(sb + 1 * ARRB64 + so0, Al + ga0);  cp16(sb + 1 * ARRB64 + so1, Al + ga1);
        cp16(sb + 2 * ARRB64 + so0, Bh + gb0);  cp16(sb + 2 * ARRB64 + so1, Bh + gb1);
        cp16(sb + 3 * ARRB64 + so0, Bl + gb0);  cp16(sb + 3 * ARRB64 + so1, Bl + gb1);
        cp_commit();
    }

    for (int s = 0; s < NST; s++) {
        if (s < NST - 1) cp_wait1(); else cp_wait0();
        __syncthreads();

        const __nv_bfloat16* st =
            reinterpret_cast<const __nv_bfloat16*>(sm + (size_t)(s & 1) * STG64);
        const __nv_bfloat16* sAh = st;
        const __nv_bfloat16* sAl = st + ARRB64 / 2;
        const __nv_bfloat16* sBh = st + 2 * (ARRB64 / 2);
        const __nv_bfloat16* sBl = st + 3 * (ARRB64 / 2);

#pragma unroll
        for (int ks = 0; ks < KC; ks += 16) {
            wmma::fragment<wmma::matrix_a, 16, 16, 16, __nv_bfloat16,
                           wmma::row_major> fAh, fAl;
            wmma::load_matrix_sync(fAh, sAh + ms * PE + ks, PE);
            wmma::load_matrix_sync(fAl, sAl + ms * PE + ks, PE);
#pragma unroll
            for (int j = 0; j < 2; j++) {
                wmma::fragment<wmma::matrix_b, 16, 16, 16, __nv_bfloat16,
                               wmma::col_major> fBh, fBl;
                const int nr = nb + j * 16;
                wmma::load_matrix_sync(fBh, sBh + nr * PE + ks, PE);
                wmma::load_matrix_sync(fBl, sBl + nr * PE + ks, PE);
                wmma::mma_sync(fC[j], fAh, fBh, fC[j]);
                wmma::mma_sync(fC[j], fAh, fBl, fC[j]);
                wmma::mma_sync(fC[j], fAl, fBh, fC[j]);
            }
        }
        __syncthreads();

        if (s + 2 < NST) {
            const int kt = (s + 2) * KC;
            const uint32_t sb = sbase + (uint32_t)(s & 1) * STG64;
            const size_t ga0 = (size_t)(m0 + r0) * H + kt + c0 * 8;
            const size_t ga1 = (size_t)(m0 + r1) * H + kt + c1 * 8;
            const size_t gb0 = (size_t)r0 * H + kt + c0 * 8;
            const size_t gb1 = (size_t)r1 * H + kt + c1 * 8;
            cp16(sb + 0 * ARRB64 + so0, Ah + ga0);  cp16(sb + 0 * ARRB64 + so1, Ah + ga1);
            cp16(sb + 1 * ARRB64 + so0, Al + ga0);  cp16(sb + 1 * ARRB64 + so1, Al + ga1);
            cp16(sb + 2 * ARRB64 + so0, Bh + gb0);  cp16(sb + 2 * ARRB64 + so1, Bh + gb1);
            cp16(sb + 3 * ARRB64 + so0, Bl + gb0);  cp16(sb + 3 * ARRB64 + so1, Bl + gb1);
            cp_commit();
        }
    }

    wmma::store_matrix_sync(sC + ms * 68 + nb,      fC[0], 68, wmma::mem_row_major);
    wmma::store_matrix_sync(sC + ms * 68 + nb + 16, fC[1], 68, wmma::mem_row_major);
    __syncthreads();
}

// ---------------- proj GEMM mainloop (BM=128) ----------------------------------
// smem stage layout: Ah[128] | Al[128] | Bh[64] | Bl[64]  (pitch 144B rows)
__device__ __forceinline__ void gemm128(
    const __nv_bfloat16* __restrict__ Ah, const __nv_bfloat16* __restrict__ Al,
    const __nv_bfloat16* __restrict__ Bh, const __nv_bfloat16* __restrict__ Bl,
    int m0, char* sm, float* sC)
{
    const int tid = threadIdx.x;
    const int wid = tid >> 5;
    const int ms = (wid & 3) * 32;      // m strip of 32
    const int nb = (wid >> 2) * 32;     // n half
    const uint32_t sbase = smem_u32(sm);

    const int ar = tid >> 1;                       // A rows: tid/2 (+128 offsets)
    const int ac = tid & 1;                        // not used directly; see below
    (void)ar; (void)ac;
    // A: 1024 vecs/array -> 4 per thread; B: 512 vecs/array -> 2 per thread
    const int c0 = tid & 7;
    const uint32_t soA[4] = {
        (uint32_t)(((tid + 0)   >> 3) * ROWB + c0 * 16),
        (uint32_t)(((tid + 256) >> 3) * ROWB + c0 * 16),
        (uint32_t)(((tid + 512) >> 3) * ROWB + c0 * 16),
        (uint32_t)(((tid + 768) >> 3) * ROWB + c0 * 16)
    };
    const int rA[4] = { (tid + 0) >> 3, (tid + 256) >> 3,
                        (tid + 512) >> 3, (tid + 768) >> 3 };

    wmma::fragment<wmma::accumulator, 16, 16, 16, float> fC[2][2];
#pragma unroll
    for (int i = 0; i < 2; i++)
#pragma unroll
        for (int j = 0; j < 2; j++) wmma::fill_fragment(fC[i][j], 0.0f);

#pragma unroll
    for (int s = 0; s < 2; s++) {
        const int kt = s * KC;
        const uint32_t sb = sbase + (uint32_t)s * STG128;
#pragma unroll
        for (int v = 0; v < 4; v++) {
            const size_t ga = (size_t)(m0 + rA[v]) * H + kt + c0 * 8;
            cp16(sb + 0 * ARRB128 + soA[v], Ah + ga);
            cp16(sb + 1 * ARRB128 + soA[v], Al + ga);
        }
#pragma unroll
        for (int v = 0; v < 2; v++) {
            const size_t gb = (size_t)rA[v] * H + kt + c0 * 8;
            cp16(sb + 2 * ARRB128 + soA[v], Bh + gb);
            cp16(sb + 2 * ARRB128 + ARRB64 + soA[v], Bl + gb);
        }
        cp_commit();
    }

    for (int s = 0; s < NST; s++) {
        if (s < NST - 1) cp_wait1(); else cp_wait0();
        __syncthreads();

        const __nv_bfloat16* st =
            reinterpret_cast<const __nv_bfloat16*>(sm + (size_t)(s & 1) * STG128);
        const __nv_bfloat16* sAh = st;
        const __nv_bfloat16* sAl = st + ARRB128 / 2;
        const __nv_bfloat16* sBh = st + 2 * (ARRB128 / 2);
        const __nv_bfloat16* sBl = st + 2 * (ARRB128 / 2) + ARRB64 / 2;

#pragma unroll
        for (int ks = 0; ks < KC; ks += 16) {
            wmma::fragment<wmma::matrix_a, 16, 16, 16, __nv_bfloat16,
                           wmma::row_major> fAh[2], fAl[2];
#pragma unroll
            for (int i = 0; i < 2; i++) {
                wmma::load_matrix_sync(fAh[i], sAh + (ms + i * 16) * PE + ks, PE);
                wmma::load_matrix_sync(fAl[i], sAl + (ms + i * 16) * PE + ks, PE);
            }
#pragma unroll
            for (int j = 0; j < 2; j++) {
                wmma::fragment<wmma::matrix_b, 16, 16, 16, __nv_bfloat16,
                               wmma::col_major> fBh, fBl;
                const int nr = nb + j * 16;
                wmma::load_matrix_sync(fBh, sBh + nr * PE + ks, PE);
                wmma::load_matrix_sync(fBl, sBl + nr * PE + ks, PE);
#pragma unroll
                for (int i = 0; i < 2; i++) {
                    wmma::mma_sync(fC[i][j], fAh[i], fBh, fC[i][j]);
                    wmma::mma_sync(fC[i][j], fAh[i], fBl, fC[i][j]);
                    wmma::mma_sync(fC[i][j], fAl[i], fBh, fC[i][j]);
                }
            }
        }
        __syncthreads();

        if (s + 2 < NST) {
            const int kt = (s + 2) * KC;
            const uint32_t sb = sbase + (uint32_t)(s & 1) * STG128;
#pragma unroll
            for (int v = 0; v < 4; v++) {
                const size_t ga = (size_t)(m0 + rA[v]) * H + kt + c0 * 8;
                cp16(sb + 0 * ARRB128 + soA[v], Ah + ga);
                cp16(sb + 1 * ARRB128 + soA[v], Al + ga);
            }
#pragma unroll
            for (int v = 0; v < 2; v++) {
                const size_t gb = (size_t)rA[v] * H + kt + c0 * 8;
                cp16(sb + 2 * ARRB128 + soA[v], Bh + gb);
                cp16(sb + 2 * ARRB128 + ARRB64 + soA[v], Bl + gb);
            }
            cp_commit();
        }
    }

#pragma unroll
    for (int i = 0; i < 2; i++)
#pragma unroll
        for (int j = 0; j < 2; j++)
            wmma::store_matrix_sync(sC + (ms + i * 16) * 68 + nb + j * 16,
                                    fC[i][j], 68, wmma::mem_row_major);
    __syncthreads();
}

// ---------------- projection kernel (BM=128) -----------------------------------
__global__ __launch_bounds__(256)
void proj_tc(int useX0, float* __restrict__ dst, int t,
             const float* __restrict__ bias)
{
    extern __shared__ char sm[];
    float* sC = reinterpret_cast<float*>(sm);
    const int m0 = blockIdx.x * 128;

    const __nv_bfloat16* Bh = useX0 ? g_xh : g_hh;
    const __nv_bfloat16* Bl = useX0 ? g_xl : g_hl;
    gemm128(g_Wout_h, g_Wout_l, Bh, Bl, m0, sm, sC);

    const int ml = threadIdx.x & 127;
    const int nlb = threadIdx.x >> 7;         // 0..1
    const int gm = m0 + ml;
    const float bb = bias[gm];
#pragma unroll
    for (int r = 0; r < 32; r++) {
        const int n = nlb + r * 2;
        dst[((size_t)n * T + t) * (size_t)V + gm] = sC[ml * 68 + n] + bb;
    }
}

// ---------------- LSTM gates kernel (pass-parallel, BM=64) ---------------------
__global__ __launch_bounds__(256)
void lstm_tc()
{
    extern __shared__ char sm[];
    float* sC = reinterpret_cast<float*>(sm);
    const int pass = blockIdx.x >> 6;
    const int m0 = (blockIdx.x & 63) * 64;

    const __nv_bfloat16* Ah = pass ? g_Whh_h : g_Wih_h;
    const __nv_bfloat16* Al = pass ? g_Whh_l : g_Wih_l;
    const __nv_bfloat16* Bh = pass ? g_hh : g_xh;
    const __nv_bfloat16* Bl = pass ? g_hl : g_xl;
    gemm64(Ah, Al, Bh, Bl, m0, sm, sC);

    float* gp = pass ? g_gp1 : g_gp0;
    const int ml = threadIdx.x & 63;
    const int nlb = threadIdx.x >> 6;
    const int gm = m0 + ml;
#pragma unroll
    for (int r = 0; r < 16; r++) {
        const int n = nlb + r * 4;
        gp[(size_t)n * G4 + gm] = sC[ml * 68 + n];
    }
}

// ---------------- weight pre-split ---------------------------------------------
__global__ void split_weights(const float* __restrict__ src, int which, int n4) {
    int i4 = blockIdx.x * blockDim.x + threadIdx.x;
    if (i4 >= n4) return;
    __nv_bfloat16* dh;
    __nv_bfloat16* dl;
    if (which == 0)      { dh = g_Wout_h; dl = g_Wout_l; }
    else if (which == 1) { dh = g_Wih_h;  dl = g_Wih_l; }
    else                 { dh = g_Whh_h;  dl = g_Whh_l; }
    float4 v = reinterpret_cast<const float4*>(src)[i4];
    __nv_bfloat16 h0, l0, h1, l1, h2, l2, h3, l3;
    split_pair(v.x, h0, l0);
    split_pair(v.y, h1, l1);
    split_pair(v.z, h2, l2);
    split_pair(v.w, h3, l3);
    size_t o = (size_t)i4 * 4;
    dh[o] = h0; dh[o + 1] = h1; dh[o + 2] = h2; dh[o + 3] = h3;
    dl[o] = l0; dl[o + 1] = l1; dl[o + 2] = l2; dl[o + 3] = l3;
}

// ---------------- small kernels --------------------------------------------------
__global__ void init_kernel(const float* __restrict__ h0,
                            const float* __restrict__ c0,
                            const float* __restrict__ embed,
                            float* __restrict__ out, int mode) {
    int idx = blockIdx.x * blockDim.x + threadIdx.x;
    if (idx < B * H) {
        g_c[idx] = c0[idx];
        __nv_bfloat16 hi, lo;
        split_pair(h0[idx], hi, lo);
        g_hh[idx] = hi;
        g_hl[idx] = lo;
        split_pair(embed[(size_t)SOS * H + (idx & (H - 1))], hi, lo);
        g_xh[idx] = hi;
        g_xl[idx] = lo;
    }
    if (idx < B) {
        g_sym[idx] = SOS;
        if (mode) out[(size_t)B * T * V + (size_t)idx * T + 0] = (float)SOS;
    }
}

__global__ void fill_zero(float* __restrict__ p, int n) {
    int i = blockIdx.x * blockDim.x + threadIdx.x;
    if (i < n) p[i] = 0.0f;
}

__global__ void lstm_act_kernel(const float* __restrict__ b_ih,
                                const float* __restrict__ b_hh) {
    int idx = blockIdx.x * blockDim.x + threadIdx.x;   // B*H
    int b = idx >> 10;
    int j = idx & (H - 1);
    const size_t base = (size_t)b * G4;
    float gi = g_gp0[base + j]        + g_gp1[base + j]        + b_ih[j]        + b_hh[j];
    float gf = g_gp0[base + j + 1024] + g_gp1[base + j + 1024] + b_ih[j + 1024] + b_hh[j + 1024];
    float gg = g_gp0[base + j + 2048] + g_gp1[base + j + 2048] + b_ih[j + 2048] + b_hh[j + 2048];
    float go = g_gp0[base + j + 3072] + g_gp1[base + j + 3072] + b_ih[j + 3072] + b_hh[j + 3072];
    float c  = g_c[idx];
    float si = 1.0f / (1.0f + expf(-gi));
    float sf = 1.0f / (1.0f + expf(-gf));
    float so = 1.0f / (1.0f + expf(-go));
    float c2 = sf * c + si * tanhf(gg);
    float h2 = so * tanhf(c2);
    g_c[idx] = c2;
    __nv_bfloat16 hi, lo;
    split_pair(h2, hi, lo);
    g_hh[idx] = hi;
    g_hl[idx] = lo;
}

// argmax + fused embed-gather for next step's x
__global__ void argmax_kernel(float* __restrict__ out,
                              const float* __restrict__ embed,
                              int t, int mode) {
    int b = blockIdx.x;
    const float4* row4 = reinterpret_cast<const float4*>(
        out + ((size_t)b * T + t) * (size_t)V);
    float best = -FLT_MAX;
    int bi = 0;
    for (int n4 = threadIdx.x; n4 < V / 4; n4 += 256) {
        float4 v = row4[n4];
        int n = n4 * 4;
        if (v.x > best) { best = v.x; bi = n; }
        if (v.y > best) { best = v.y; bi = n + 1; }
        if (v.z > best) { best = v.z; bi = n + 2; }
        if (v.w > best) { best = v.w; bi = n + 3; }
    }
    __shared__ float sv[256];
    __shared__ int   si[256];
    sv[threadIdx.x] = best;
    si[threadIdx.x] = bi;
    __syncthreads();
    for (int s = 128; s > 0; s >>= 1) {
        if (threadIdx.x < s) {
            float ov = sv[threadIdx.x + s];
            int   oi = si[threadIdx.x + s];
            if (ov > sv[threadIdx.x] ||
                (ov == sv[threadIdx.x] && oi < si[threadIdx.x])) {
                sv[threadIdx.x] = ov;
                si[threadIdx.x] = oi;
            }
        }
        __syncthreads();
    }
    const int sym = si[0];
    if (threadIdx.x == 0) {
        g_sym[b] = sym;
        if (mode) out[(size_t)B * T * V + (size_t)b * T + t] = (float)sym;
    }
    // fused gather+split of embed[sym] -> x for the next LSTM step
    const float4* erow = reinterpret_cast<const float4*>(embed + (size_t)sym * H);
#pragma unroll
    for (int q = 0; q < 1; q++) {
        float4 v = erow[threadIdx.x];
        int j = threadIdx.x * 4;
        __nv_bfloat16 hi, lo;
        split_pair(v.x, hi, lo); g_xh[b * H + j]     = hi; g_xl[b * H + j]     = lo;
        split_pair(v.y, hi, lo); g_xh[b * H + j + 1] = hi; g_xl[b * H + j + 1] = lo;
        split_pair(v.z, hi, lo); g_xh[b * H + j + 2] = hi; g_xl[b * H + j + 2] = lo;
        split_pair(v.w, hi, lo); g_xh[b * H + j + 3] = hi; g_xl[b * H + j + 3] = lo;
    }
}

// ---------------- launch ----------------------------------------------------------
extern "C" void kernel_launch(void* const* d_in, const int* in_sizes, int n_in,
                              void* d_out, int out_size) {
    const float* h0    = (const float*)d_in[1];
    const float* c0    = (const float*)d_in[2];
    const float* embed = (const float*)d_in[5];
    const float* w_ih  = (const float*)d_in[6];
    const float* w_hh  = (const float*)d_in[7];
    const float* b_ih  = (const float*)d_in[8];
    const float* b_hh  = (const float*)d_in[9];
    const float* w_out = (const float*)d_in[10];
    const float* b_out = (const float*)d_in[11];
    float* out = (float*)d_out;

    static int attr_done = 0;
    if (!attr_done) {
        cudaFuncSetAttribute(proj_tc, cudaFuncAttributeMaxDynamicSharedMemorySize, DSMEM_P);
        cudaFuncSetAttribute(lstm_tc, cudaFuncAttributeMaxDynamicSharedMemorySize, DSMEM_L);
        attr_done = 1;
    }

    const long long BTV = (long long)B * T * V;
    long long extra = (long long)out_size - BTV;
    int mode = (extra >= (long long)(B * T)) ? 1 : 0;

    init_kernel<<<(B * H + 511) / 512, 512>>>(h0, c0, embed, out, mode);

    split_weights<<<(V * H / 4 + 255) / 256, 256>>>(w_out, 0, V * H / 4);
    split_weights<<<(G4 * H / 4 + 255) / 256, 256>>>(w_ih, 1, G4 * H / 4);
    split_weights<<<(G4 * H / 4 + 255) / 256, 256>>>(w_hh, 2, G4 * H / 4);

    long long zstart = BTV + (mode ? (long long)(B * T) : 0);
    long long zcount = (long long)out_size - zstart;
    if (zcount > 0)
        fill_zero<<<(int)((zcount + 255) / 256), 256>>>(out + zstart, (int)zcount);

    // t = 0: logits from embed[SOS] (g_xh/g_xl seeded by init)
    proj_tc<<<V / 128, 256, DSMEM_P>>>(1, out, 0, b_out);

    for (int t = 1; t < T; t++) {
        lstm_tc<<<128, 256, DSMEM_L>>>();
        lstm_act_kernel<<<(B * H) / 256, 256>>>(b_ih, b_hh);
        proj_tc<<<V / 128, 256, DSMEM_P>>>(0, out, t, b_out);
        argmax_kernel<<<B, 256>>>(out, embed, t, mode);
    }
}

// round 10
// speedup vs baseline: 3.6521x; 1.1989x over previous
#include <cuda_runtime.h>
#include <cuda_fp16.h>
#include <mma.h>
#include <cstdint>
#include <cfloat>

using namespace nvcuda;

#define B   64
#define H   1024
#define V   32000
#define T   40
#define G4  4096
#define SOS 1

#define KC   64
#define PE   72                     // smem pitch in half elements
#define ROWB 144                    // pitch bytes
#define NST  (H / KC)               // 16 stages
#define NPART (V / 128)             // 250 proj blocks

// ---- LSTM geometry (BM=64) ----
#define ARRB64 (64 * ROWB)          // 9216
#define STG64  (4 * ARRB64)         // 36864
#define DSMEM_L (2 * STG64)         // 73728

// ---- proj geometry (BM=128) ----
#define ARRB128 (128 * ROWB)        // 18432
#define STG128  (2 * ARRB128 + 2 * ARRB64)   // 55296
#define DSMEM_P (2 * STG128)        // 110592

// ---------------- persistent device state (device-code access ONLY) ----------
__device__ __align__(16) __half g_Wout_h[(size_t)V * H];
__device__ __align__(16) __half g_Wout_l[(size_t)V * H];
__device__ __align__(16) __half g_Wih_h[(size_t)G4 * H];
__device__ __align__(16) __half g_Wih_l[(size_t)G4 * H];
__device__ __align__(16) __half g_Whh_h[(size_t)G4 * H];
__device__ __align__(16) __half g_Whh_l[(size_t)G4 * H];
__device__ __align__(16) __half g_xh[B * H],  g_xl[B * H];
__device__ __align__(16) __half g_hh[B * H],  g_hl[B * H];
__device__ float g_c[B * H];
__device__ float g_gp0[B * G4];
__device__ float g_gp1[B * G4];
__device__ float g_pv[NPART * B];   // proj partial argmax values
__device__ int   g_pi[NPART * B];   // proj partial argmax indices

// ---------------- helpers ------------------------------------------------------
__device__ __forceinline__ uint32_t smem_u32(const void* p) {
    uint32_t a;
    asm("{ .reg .u64 t; cvta.to.shared.u64 t, %1; cvt.u32.u64 %0, t; }"
        : "=r"(a) : "l"(p));
    return a;
}
__device__ __forceinline__ void cp16(uint32_t s, const void* g) {
    asm volatile("cp.async.cg.shared.global [%0], [%1], 16;" :: "r"(s), "l"(g));
}
__device__ __forceinline__ void cp_commit() {
    asm volatile("cp.async.commit_group;" ::: "memory");
}
__device__ __forceinline__ void cp_wait1() {
    asm volatile("cp.async.wait_group 1;" ::: "memory");
}
__device__ __forceinline__ void cp_wait0() {
    asm volatile("cp.async.wait_group 0;" ::: "memory");
}
__device__ __forceinline__ void split_pair(float x, __half& hi, __half& lo) {
    hi = __float2half_rn(x);
    lo = __float2half_rn(x - __half2float(hi));
}

// ---------------- LSTM GEMM mainloop (BM=64) -----------------------------------
// Main term Ah*Bh in fp32 accum; corrections Ah*Bl + Al*Bh in fp16 accum.
__device__ __forceinline__ void gemm64(
    const __half* __restrict__ Ah, const __half* __restrict__ Al,
    const __half* __restrict__ Bh, const __half* __restrict__ Bl,
    int m0, char* sm, float* sC, __half* sCh)
{
    const int tid = threadIdx.x;
    const int wid = tid >> 5;
    const int ms = (wid & 3) * 16;
    const int nb = (wid >> 2) * 32;
    const uint32_t sbase = smem_u32(sm);

    const int r0 = tid >> 3,         c0 = tid & 7;
    const int r1 = (tid + 256) >> 3, c1 = tid & 7;
    const uint32_t so0 = (uint32_t)(r0 * ROWB + c0 * 16);
    const uint32_t so1 = (uint32_t)(r1 * ROWB + c1 * 16);

    wmma::fragment<wmma::accumulator, 16, 16, 16, float> fC[2];
    wmma::fragment<wmma::accumulator, 16, 16, 16, __half> fE[2];
    wmma::fill_fragment(fC[0], 0.0f);
    wmma::fill_fragment(fC[1], 0.0f);
    wmma::fill_fragment(fE[0], __float2half(0.0f));
    wmma::fill_fragment(fE[1], __float2half(0.0f));

#pragma unroll
    for (int s = 0; s < 2; s++) {
        const int kt = s * KC;
        const uint32_t sb = sbase + (uint32_t)s * STG64;
        const size_t ga0 = (size_t)(m0 + r0) * H + kt + c0 * 8;
        const size_t ga1 = (size_t)(m0 + r1) * H + kt + c1 * 8;
        const size_t gb0 = (size_t)r0 * H + kt + c0 * 8;
        const size_t gb1 = (size_t)r1 * H + kt + c1 * 8;
        cp16(sb + 0 * ARRB64 + so0, Ah + ga0);  cp16(sb + 0 * ARRB64 + so1, Ah + ga1);
        cp16(sb + 1 * ARRB64 + so0, Al + ga0);  cp16(sb + 1 * ARRB64 + so1, Al + ga1);
        cp16(sb + 2 * ARRB64 + so0, Bh + gb0);  cp16(sb + 2 * ARRB64 + so1, Bh + gb1);
        cp16(sb + 3 * ARRB64 + so0, Bl + gb0);  cp16(sb + 3 * ARRB64 + so1, Bl + gb1);
        cp_commit();
    }

    for (int s = 0; s < NST; s++) {
        if (s < NST - 1) cp_wait1(); else cp_wait0();
        __syncthreads();

        const __half* st =
            reinterpret_cast<const __half*>(sm + (size_t)(s & 1) * STG64);
        const __half* sAh = st;
        const __half* sAl = st + ARRB64 / 2;
        const __half* sBh = st + 2 * (ARRB64 / 2);
        const __half* sBl = st + 3 * (ARRB64 / 2);

#pragma unroll
        for (int ks = 0; ks < KC; ks += 16) {
            wmma::fragment<wmma::matrix_a, 16, 16, 16, __half,
                           wmma::row_major> fAh, fAl;
            wmma::load_matrix_sync(fAh, sAh + ms * PE + ks, PE);
            wmma::load_matrix_sync(fAl, sAl + ms * PE + ks, PE);
#pragma unroll
            for (int j = 0; j < 2; j++) {
                wmma::fragment<wmma::matrix_b, 16, 16, 16, __half,
                               wmma::col_major> fBh, fBl;
                const int nr = nb + j * 16;
                wmma::load_matrix_sync(fBh, sBh + nr * PE + ks, PE);
                wmma::load_matrix_sync(fBl, sBl + nr * PE + ks, PE);
                wmma::mma_sync(fC[j], fAh, fBh, fC[j]);       // main (fp32 acc)
                wmma::mma_sync(fE[j], fAh, fBl, fE[j]);       // corr (fp16 acc)
                wmma::mma_sync(fE[j], fAl, fBh, fE[j]);
            }
        }
        __syncthreads();

        if (s + 2 < NST) {
            const int kt = (s + 2) * KC;
            const uint32_t sb = sbase + (uint32_t)(s & 1) * STG64;
            const size_t ga0 = (size_t)(m0 + r0) * H + kt + c0 * 8;
            const size_t ga1 = (size_t)(m0 + r1) * H + kt + c1 * 8;
            const size_t gb0 = (size_t)r0 * H + kt + c0 * 8;
            const size_t gb1 = (size_t)r1 * H + kt + c1 * 8;
            cp16(sb + 0 * ARRB64 + so0, Ah + ga0);  cp16(sb + 0 * ARRB64 + so1, Ah + ga1);
            cp16(sb + 1 * ARRB64 + so0, Al + ga0);  cp16(sb + 1 * ARRB64 + so1, Al + ga1);
            cp16(sb + 2 * ARRB64 + so0, Bh + gb0);  cp16(sb + 2 * ARRB64 + so1, Bh + gb1);
            cp16(sb + 3 * ARRB64 + so0, Bl + gb0);  cp16(sb + 3 * ARRB64 + so1, Bl + gb1);
            cp_commit();
        }
    }

    wmma::store_matrix_sync(sC + ms * 68 + nb,       fC[0], 68, wmma::mem_row_major);
    wmma::store_matrix_sync(sC + ms * 68 + nb + 16,  fC[1], 68, wmma::mem_row_major);
    wmma::store_matrix_sync(sCh + ms * 72 + nb,      fE[0], 72, wmma::mem_row_major);
    wmma::store_matrix_sync(sCh + ms * 72 + nb + 16, fE[1], 72, wmma::mem_row_major);
    __syncthreads();
}

// ---------------- proj GEMM mainloop (BM=128) ----------------------------------
__device__ __forceinline__ void gemm128(
    const __half* __restrict__ Ah, const __half* __restrict__ Al,
    const __half* __restrict__ Bh, const __half* __restrict__ Bl,
    int m0, char* sm, float* sC, __half* sCh)
{
    const int tid = threadIdx.x;
    const int wid = tid >> 5;
    const int ms = (wid & 3) * 32;
    const int nb = (wid >> 2) * 32;
    const uint32_t sbase = smem_u32(sm);

    const int c0 = tid & 7;
    const uint32_t soA[4] = {
        (uint32_t)(((tid + 0)   >> 3) * ROWB + c0 * 16),
        (uint32_t)(((tid + 256) >> 3) * ROWB + c0 * 16),
        (uint32_t)(((tid + 512) >> 3) * ROWB + c0 * 16),
        (uint32_t)(((tid + 768) >> 3) * ROWB + c0 * 16)
    };
    const int rA[4] = { (tid + 0) >> 3, (tid + 256) >> 3,
                        (tid + 512) >> 3, (tid + 768) >> 3 };

    wmma::fragment<wmma::accumulator, 16, 16, 16, float> fC[2][2];
    wmma::fragment<wmma::accumulator, 16, 16, 16, __half> fE[2][2];
#pragma unroll
    for (int i = 0; i < 2; i++)
#pragma unroll
        for (int j = 0; j < 2; j++) {
            wmma::fill_fragment(fC[i][j], 0.0f);
            wmma::fill_fragment(fE[i][j], __float2half(0.0f));
        }

#pragma unroll
    for (int s = 0; s < 2; s++) {
        const int kt = s * KC;
        const uint32_t sb = sbase + (uint32_t)s * STG128;
#pragma unroll
        for (int v = 0; v < 4; v++) {
            const size_t ga = (size_t)(m0 + rA[v]) * H + kt + c0 * 8;
            cp16(sb + 0 * ARRB128 + soA[v], Ah + ga);
            cp16(sb + 1 * ARRB128 + soA[v], Al + ga);
        }
#pragma unroll
        for (int v = 0; v < 2; v++) {
            const size_t gb = (size_t)rA[v] * H + kt + c0 * 8;
            cp16(sb + 2 * ARRB128 + soA[v], Bh + gb);
            cp16(sb + 2 * ARRB128 + ARRB64 + soA[v], Bl + gb);
        }
        cp_commit();
    }

    for (int s = 0; s < NST; s++) {
        if (s < NST - 1) cp_wait1(); else cp_wait0();
        __syncthreads();

        const __half* st =
            reinterpret_cast<const __half*>(sm + (size_t)(s & 1) * STG128);
        const __half* sAh = st;
        const __half* sAl = st + ARRB128 / 2;
        const __half* sBh = st + 2 * (ARRB128 / 2);
        const __half* sBl = st + 2 * (ARRB128 / 2) + ARRB64 / 2;

#pragma unroll
        for (int ks = 0; ks < KC; ks += 16) {
            wmma::fragment<wmma::matrix_a, 16, 16, 16, __half,
                           wmma::row_major> fAh[2], fAl[2];
#pragma unroll
            for (int i = 0; i < 2; i++) {
                wmma::load_matrix_sync(fAh[i], sAh + (ms + i * 16) * PE + ks, PE);
                wmma::load_matrix_sync(fAl[i], sAl + (ms + i * 16) * PE + ks, PE);
            }
#pragma unroll
            for (int j = 0; j < 2; j++) {
                wmma::fragment<wmma::matrix_b, 16, 16, 16, __half,
                               wmma::col_major> fBh, fBl;
                const int nr = nb + j * 16;
                wmma::load_matrix_sync(fBh, sBh + nr * PE + ks, PE);
                wmma::load_matrix_sync(fBl, sBl + nr * PE + ks, PE);
#pragma unroll
                for (int i = 0; i < 2; i++) {
                    wmma::mma_sync(fC[i][j], fAh[i], fBh, fC[i][j]);
                    wmma::mma_sync(fE[i][j], fAh[i], fBl, fE[i][j]);
                    wmma::mma_sync(fE[i][j], fAl[i], fBh, fE[i][j]);
                }
            }
        }
        __syncthreads();

        if (s + 2 < NST) {
            const int kt = (s + 2) * KC;
            const uint32_t sb = sbase + (uint32_t)(s & 1) * STG128;
#pragma unroll
            for (int v = 0; v < 4; v++) {
                const size_t ga = (size_t)(m0 + rA[v]) * H + kt + c0 * 8;
                cp16(sb + 0 * ARRB128 + soA[v], Ah + ga);
                cp16(sb + 1 * ARRB128 + soA[v], Al + ga);
            }
#pragma unroll
            for (int v = 0; v < 2; v++) {
                const size_t gb = (size_t)rA[v] * H + kt + c0 * 8;
                cp16(sb + 2 * ARRB128 + soA[v], Bh + gb);
                cp16(sb + 2 * ARRB128 + ARRB64 + soA[v], Bl + gb);
            }
            cp_commit();
        }
    }

#pragma unroll
    for (int i = 0; i < 2; i++)
#pragma unroll
        for (int j = 0; j < 2; j++) {
            wmma::store_matrix_sync(sC + (ms + i * 16) * 68 + nb + j * 16,
                                    fC[i][j], 68, wmma::mem_row_major);
            wmma::store_matrix_sync(sCh + (ms + i * 16) * 72 + nb + j * 16,
                                    fE[i][j], 72, wmma::mem_row_major);
        }
    __syncthreads();
}

// ---------------- projection kernel (BM=128) + partial argmax ------------------
__global__ __launch_bounds__(256)
void proj_tc(int useX0, float* __restrict__ dst, int t,
             const float* __restrict__ bias)
{
    extern __shared__ char sm[];
    float* sC  = reinterpret_cast<float*>(sm);
    __half* sCh = reinterpret_cast<__half*>(sm + 128 * 68 * 4);
    __shared__ float sBias[128];
    __shared__ float sPV[256];
    __shared__ int   sPI[256];

    const int tid = threadIdx.x;
    const int m0 = blockIdx.x * 128;
    if (tid < 128) sBias[tid] = bias[m0 + tid];

    const __half* Bh = useX0 ? g_xh : g_hh;
    const __half* Bl = useX0 ? g_xl : g_hl;
    gemm128(g_Wout_h, g_Wout_l, Bh, Bl, m0, sm, sC, sCh);

    // write logits (thread = vocab row, coalesced across gm)
    const int ml = tid & 127;
    const int nlb = tid >> 7;          // 0..1
    const int gm = m0 + ml;
    const float bb = sBias[ml];
#pragma unroll
    for (int r = 0; r < 32; r++) {
        const int n = nlb + r * 2;
        dst[((size_t)n * T + t) * (size_t)V + gm] =
            sC[ml * 68 + n] + __half2float(sCh[ml * 72 + n]) + bb;
    }

    // partial argmax over this block's 128 vocab rows, per batch column
    const int n = tid & 63, q = tid >> 6;
    float bv = -FLT_MAX;
    int bi = 0;
    for (int r = q * 32; r < q * 32 + 32; r++) {
        float v = sC[r * 68 + n] + __half2float(sCh[r * 72 + n]) + sBias[r];
        if (v > bv) { bv = v; bi = m0 + r; }
    }
    sPV[tid] = bv;
    sPI[tid] = bi;
    __syncthreads();
    if (tid < 64) {
        float v0 = sPV[tid];
        int   i0 = sPI[tid];
#pragma unroll
        for (int qq = 1; qq < 4; qq++) {
            float v = sPV[tid + qq * 64];
            int   i = sPI[tid + qq * 64];
            if (v > v0 || (v == v0 && i < i0)) { v0 = v; i0 = i; }
        }
        g_pv[blockIdx.x * B + tid] = v0;
        g_pi[blockIdx.x * B + tid] = i0;
    }
}

// ---------------- LSTM gates kernel (pass-parallel, BM=64) ---------------------
__global__ __launch_bounds__(256)
void lstm_tc()
{
    extern __shared__ char sm[];
    float* sC  = reinterpret_cast<float*>(sm);
    __half* sCh = reinterpret_cast<__half*>(sm + 64 * 68 * 4);
    const int pass = blockIdx.x >> 6;
    const int m0 = (blockIdx.x & 63) * 64;

    const __half* Ah = pass ? g_Whh_h : g_Wih_h;
    const __half* Al = pass ? g_Whh_l : g_Wih_l;
    const __half* Bh = pass ? g_hh : g_xh;
    const __half* Bl = pass ? g_hl : g_xl;
    gemm64(Ah, Al, Bh, Bl, m0, sm, sC, sCh);

    float* gp = pass ? g_gp1 : g_gp0;
    const int ml = threadIdx.x & 63;
    const int nlb = threadIdx.x >> 6;
    const int gm = m0 + ml;
#pragma unroll
    for (int r = 0; r < 16; r++) {
        const int n = nlb + r * 4;
        gp[(size_t)n * G4 + gm] = sC[ml * 68 + n] + __half2float(sCh[ml * 72 + n]);
    }
}

// ---------------- weight pre-split ---------------------------------------------
__global__ void split_weights(const float* __restrict__ src, int which, int n4) {
    int i4 = blockIdx.x * blockDim.x + threadIdx.x;
    if (i4 >= n4) return;
    __half* dh;
    __half* dl;
    if (which == 0)      { dh = g_Wout_h; dl = g_Wout_l; }
    else if (which == 1) { dh = g_Wih_h;  dl = g_Wih_l; }
    else                 { dh = g_Whh_h;  dl = g_Whh_l; }
    float4 v = reinterpret_cast<const float4*>(src)[i4];
    __half h0, l0, h1, l1, h2, l2, h3, l3;
    split_pair(v.x, h0, l0);
    split_pair(v.y, h1, l1);
    split_pair(v.z, h2, l2);
    split_pair(v.w, h3, l3);
    size_t o = (size_t)i4 * 4;
    dh[o] = h0; dh[o + 1] = h1; dh[o + 2] = h2; dh[o + 3] = h3;
    dl[o] = l0; dl[o + 1] = l1; dl[o + 2] = l2; dl[o + 3] = l3;
}

// ---------------- small kernels --------------------------------------------------
__global__ void init_kernel(const float* __restrict__ h0,
                            const float* __restrict__ c0,
                            const float* __restrict__ embed,
                            float* __restrict__ out, int mode) {
    int idx = blockIdx.x * blockDim.x + threadIdx.x;
    if (idx < B * H) {
        g_c[idx] = c0[idx];
        __half hi, lo;
        split_pair(h0[idx], hi, lo);
        g_hh[idx] = hi;
        g_hl[idx] = lo;
        split_pair(embed[(size_t)SOS * H + (idx & (H - 1))], hi, lo);
        g_xh[idx] = hi;
        g_xl[idx] = lo;
    }
    if (idx < B && mode)
        out[(size_t)B * T * V + (size_t)idx * T + 0] = (float)SOS;
}

__global__ void fill_zero(float* __restrict__ p, int n) {
    int i = blockIdx.x * blockDim.x + threadIdx.x;
    if (i < n) p[i] = 0.0f;
}

__global__ void lstm_act_kernel(const float* __restrict__ b_ih,
                                const float* __restrict__ b_hh) {
    int idx = blockIdx.x * blockDim.x + threadIdx.x;   // B*H
    int b = idx >> 10;
    int j = idx & (H - 1);
    const size_t base = (size_t)b * G4;
    float gi = g_gp0[base + j]        + g_gp1[base + j]        + b_ih[j]        + b_hh[j];
    float gf = g_gp0[base + j + 1024] + g_gp1[base + j + 1024] + b_ih[j + 1024] + b_hh[j + 1024];
    float gg = g_gp0[base + j + 2048] + g_gp1[base + j + 2048] + b_ih[j + 2048] + b_hh[j + 2048];
    float go = g_gp0[base + j + 3072] + g_gp1[base + j + 3072] + b_ih[j + 3072] + b_hh[j + 3072];
    float c  = g_c[idx];
    float si = 1.0f / (1.0f + expf(-gi));
    float sf = 1.0f / (1.0f + expf(-gf));
    float so = 1.0f / (1.0f + expf(-go));
    float c2 = sf * c + si * tanhf(gg);
    float h2 = so * tanhf(c2);
    g_c[idx] = c2;
    __half hi, lo;
    split_pair(h2, hi, lo);
    g_hh[idx] = hi;
    g_hl[idx] = lo;
}

// final argmax over proj partials + fused embed gather/split for next step
__global__ void argmax_final(float* __restrict__ out,
                             const float* __restrict__ embed,
                             int t, int mode) {
    const int b = blockIdx.x;
    const int tid = threadIdx.x;
    float bv = -FLT_MAX;
    int bi = 0x7fffffff;
    for (int i = tid; i < NPART; i += 256) {
        float v = g_pv[i * B + b];
        int   ix = g_pi[i * B + b];
        if (v > bv || (v == bv && ix < bi)) { bv = v; bi = ix; }
    }
    __shared__ float sv[256];
    __shared__ int   si[256];
    sv[tid] = bv;
    si[tid] = bi;
    __syncthreads();
    for (int s = 128; s > 0; s >>= 1) {
        if (tid < s) {
            float ov = sv[tid + s];
            int   oi = si[tid + s];
            if (ov > sv[tid] || (ov == sv[tid] && oi < si[tid])) {
                sv[tid] = ov;
                si[tid] = oi;
            }
        }
        __syncthreads();
    }
    const int sym = si[0];
    if (tid == 0 && mode)
        out[(size_t)B * T * V + (size_t)b * T + t] = (float)sym;
    // gather + fp16-split embed[sym] -> x for next LSTM step
    const float4* erow = reinterpret_cast<const float4*>(embed + (size_t)sym * H);
    float4 v = erow[tid];
    int j = tid * 4;
    __half hi, lo;
    split_pair(v.x, hi, lo); g_xh[b * H + j]     = hi; g_xl[b * H + j]     = lo;
    split_pair(v.y, hi, lo); g_xh[b * H + j + 1] = hi; g_xl[b * H + j + 1] = lo;
    split_pair(v.z, hi, lo); g_xh[b * H + j + 2] = hi; g_xl[b * H + j + 2] = lo;
    split_pair(v.w, hi, lo); g_xh[b * H + j + 3] = hi; g_xl[b * H + j + 3] = lo;
}

// ---------------- launch ----------------------------------------------------------
extern "C" void kernel_launch(void* const* d_in, const int* in_sizes, int n_in,
                              void* d_out, int out_size) {
    const float* h0    = (const float*)d_in[1];
    const float* c0    = (const float*)d_in[2];
    const float* embed = (const float*)d_in[5];
    const float* w_ih  = (const float*)d_in[6];
    const float* w_hh  = (const float*)d_in[7];
    const float* b_ih  = (const float*)d_in[8];
    const float* b_hh  = (const float*)d_in[9];
    const float* w_out = (const float*)d_in[10];
    const float* b_out = (const float*)d_in[11];
    float* out = (float*)d_out;

    static int attr_done = 0;
    if (!attr_done) {
        cudaFuncSetAttribute(proj_tc, cudaFuncAttributeMaxDynamicSharedMemorySize, DSMEM_P);
        cudaFuncSetAttribute(lstm_tc, cudaFuncAttributeMaxDynamicSharedMemorySize, DSMEM_L);
        attr_done = 1;
    }

    const long long BTV = (long long)B * T * V;
    long long extra = (long long)out_size - BTV;
    int mode = (extra >= (long long)(B * T)) ? 1 : 0;

    init_kernel<<<(B * H + 511) / 512, 512>>>(h0, c0, embed, out, mode);

    split_weights<<<(V * H / 4 + 255) / 256, 256>>>(w_out, 0, V * H / 4);
    split_weights<<<(G4 * H / 4 + 255) / 256, 256>>>(w_ih, 1, G4 * H / 4);
    split_weights<<<(G4 * H / 4 + 255) / 256, 256>>>(w_hh, 2, G4 * H / 4);

    long long zstart = BTV + (mode ? (long long)(B * T) : 0);
    long long zcount = (long long)out_size - zstart;
    if (zcount > 0)
        fill_zero<<<(int)((zcount + 255) / 256), 256>>>(out + zstart, (int)zcount);

    // t = 0: logits from embed[SOS] (g_xh/g_xl seeded by init; partials unused)
    proj_tc<<<V / 128, 256, DSMEM_P>>>(1, out, 0, b_out);

    for (int t = 1; t < T; t++) {
        lstm_tc<<<128, 256, DSMEM_L>>>();
        lstm_act_kernel<<<(B * H) / 256, 256>>>(b_ih, b_hh);
        proj_tc<<<V / 128, 256, DSMEM_P>>>(0, out, t, b_out);
        argmax_final<<<B, 256>>>(out, embed, t, mode);
    }
}

// round 11
// speedup vs baseline: 3.6822x; 1.0082x over previous
#include <cuda_runtime.h>
#include <cuda_fp16.h>
#include <mma.h>
#include <cstdint>
#include <cfloat>

using namespace nvcuda;

#define B   64
#define H   1024
#define V   32000
#define T   40
#define G4  4096
#define SOS 1

#define KC   64
#define PE   72                     // smem pitch in half elements
#define ROWB 144                    // pitch bytes
#define NST  (H / KC)               // 16 stages
#define NPART (V / 128)             // 250 proj blocks

// ---- LSTM geometry (BM=64) ----
#define ARRB64 (64 * ROWB)          // 9216
#define STG64  (4 * ARRB64)         // 36864
#define DSMEM_L (2 * STG64)         // 73728

// ---- proj geometry (BM=128) ----
#define ARRB128 (128 * ROWB)        // 18432
#define STG128  (2 * ARRB128 + 2 * ARRB64)   // 55296
#define DSMEM_P (2 * STG128)        // 110592

// ---------------- persistent device state (device-code access ONLY) ----------
__device__ __align__(16) __half g_Wout_h[(size_t)V * H];
__device__ __align__(16) __half g_Wout_l[(size_t)V * H];
__device__ __align__(16) __half g_Wih_h[(size_t)G4 * H];
__device__ __align__(16) __half g_Wih_l[(size_t)G4 * H];
__device__ __align__(16) __half g_Whh_h[(size_t)G4 * H];
__device__ __align__(16) __half g_Whh_l[(size_t)G4 * H];
__device__ __align__(16) __half g_xh[B * H],  g_xl[B * H];
__device__ __align__(16) __half g_hh[B * H],  g_hl[B * H];
__device__ float g_c[B * H];
__device__ float g_gp0[B * G4];
__device__ float g_gp1[B * G4];
__device__ float g_pv[NPART * B];   // proj partial argmax values
__device__ int   g_pi[NPART * B];   // proj partial argmax indices

// ---------------- helpers ------------------------------------------------------
__device__ __forceinline__ uint32_t smem_u32(const void* p) {
    uint32_t a;
    asm("{ .reg .u64 t; cvta.to.shared.u64 t, %1; cvt.u32.u64 %0, t; }"
        : "=r"(a) : "l"(p));
    return a;
}
__device__ __forceinline__ void cp16(uint32_t s, const void* g) {
    asm volatile("cp.async.cg.shared.global [%0], [%1], 16;" :: "r"(s), "l"(g));
}
__device__ __forceinline__ void cp_commit() {
    asm volatile("cp.async.commit_group;" ::: "memory");
}
__device__ __forceinline__ void cp_wait1() {
    asm volatile("cp.async.wait_group 1;" ::: "memory");
}
__device__ __forceinline__ void cp_wait0() {
    asm volatile("cp.async.wait_group 0;" ::: "memory");
}
__device__ __forceinline__ void split_pair(float x, __half& hi, __half& lo) {
    hi = __float2half_rn(x);
    lo = __float2half_rn(x - __half2float(hi));
}

// ---------------- LSTM GEMM mainloop (BM=64) -----------------------------------
__device__ __forceinline__ void gemm64(
    const __half* __restrict__ Ah, const __half* __restrict__ Al,
    const __half* __restrict__ Bh, const __half* __restrict__ Bl,
    int m0, char* sm, float* sC, __half* sCh)
{
    const int tid = threadIdx.x;
    const int wid = tid >> 5;
    const int ms = (wid & 3) * 16;
    const int nb = (wid >> 2) * 32;
    const uint32_t sbase = smem_u32(sm);

    const int r0 = tid >> 3,         c0 = tid & 7;
    const int r1 = (tid + 256) >> 3, c1 = tid & 7;
    const uint32_t so0 = (uint32_t)(r0 * ROWB + c0 * 16);
    const uint32_t so1 = (uint32_t)(r1 * ROWB + c1 * 16);

    wmma::fragment<wmma::accumulator, 16, 16, 16, float> fC[2];
    wmma::fragment<wmma::accumulator, 16, 16, 16, __half> fE[2];
    wmma::fill_fragment(fC[0], 0.0f);
    wmma::fill_fragment(fC[1], 0.0f);
    wmma::fill_fragment(fE[0], __float2half(0.0f));
    wmma::fill_fragment(fE[1], __float2half(0.0f));

#pragma unroll
    for (int s = 0; s < 2; s++) {
        const int kt = s * KC;
        const uint32_t sb = sbase + (uint32_t)s * STG64;
        const size_t ga0 = (size_t)(m0 + r0) * H + kt + c0 * 8;
        const size_t ga1 = (size_t)(m0 + r1) * H + kt + c1 * 8;
        const size_t gb0 = (size_t)r0 * H + kt + c0 * 8;
        const size_t gb1 = (size_t)r1 * H + kt + c1 * 8;
        cp16(sb + 0 * ARRB64 + so0, Ah + ga0);  cp16(sb + 0 * ARRB64 + so1, Ah + ga1);
        cp16(sb + 1 * ARRB64 + so0, Al + ga0);  cp16(sb + 1 * ARRB64 + so1, Al + ga1);
        cp16(sb + 2 * ARRB64 + so0, Bh + gb0);  cp16(sb + 2 * ARRB64 + so1, Bh + gb1);
        cp16(sb + 3 * ARRB64 + so0, Bl + gb0);  cp16(sb + 3 * ARRB64 + so1, Bl + gb1);
        cp_commit();
    }

    for (int s = 0; s < NST; s++) {
        if (s < NST - 1) cp_wait1(); else cp_wait0();
        __syncthreads();

        const __half* st =
            reinterpret_cast<const __half*>(sm + (size_t)(s & 1) * STG64);
        const __half* sAh = st;
        const __half* sAl = st + ARRB64 / 2;
        const __half* sBh = st + 2 * (ARRB64 / 2);
        const __half* sBl = st + 3 * (ARRB64 / 2);

#pragma unroll
        for (int ks = 0; ks < KC; ks += 16) {
            wmma::fragment<wmma::matrix_a, 16, 16, 16, __half,
                           wmma::row_major> fAh, fAl;
            wmma::load_matrix_sync(fAh, sAh + ms * PE + ks, PE);
            wmma::load_matrix_sync(fAl, sAl + ms * PE + ks, PE);
#pragma unroll
            for (int j = 0; j < 2; j++) {
                wmma::fragment<wmma::matrix_b, 16, 16, 16, __half,
                               wmma::col_major> fBh, fBl;
                const int nr = nb + j * 16;
                wmma::load_matrix_sync(fBh, sBh + nr * PE + ks, PE);
                wmma::load_matrix_sync(fBl, sBl + nr * PE + ks, PE);
                wmma::mma_sync(fC[j], fAh, fBh, fC[j]);       // main (fp32 acc)
                wmma::mma_sync(fE[j], fAh, fBl, fE[j]);       // corr (fp16 acc)
                wmma::mma_sync(fE[j], fAl, fBh, fE[j]);
            }
        }
        __syncthreads();

        if (s + 2 < NST) {
            const int kt = (s + 2) * KC;
            const uint32_t sb = sbase + (uint32_t)(s & 1) * STG64;
            const size_t ga0 = (size_t)(m0 + r0) * H + kt + c0 * 8;
            const size_t ga1 = (size_t)(m0 + r1) * H + kt + c1 * 8;
            const size_t gb0 = (size_t)r0 * H + kt + c0 * 8;
            const size_t gb1 = (size_t)r1 * H + kt + c1 * 8;
            cp16(sb + 0 * ARRB64 + so0, Ah + ga0);  cp16(sb + 0 * ARRB64 + so1, Ah + ga1);
            cp16(sb + 1 * ARRB64 + so0, Al + ga0);  cp16(sb + 1 * ARRB64 + so1, Al + ga1);
            cp16(sb + 2 * ARRB64 + so0, Bh + gb0);  cp16(sb + 2 * ARRB64 + so1, Bh + gb1);
            cp16(sb + 3 * ARRB64 + so0, Bl + gb0);  cp16(sb + 3 * ARRB64 + so1, Bl + gb1);
            cp_commit();
        }
    }

    wmma::store_matrix_sync(sC + ms * 68 + nb,       fC[0], 68, wmma::mem_row_major);
    wmma::store_matrix_sync(sC + ms * 68 + nb + 16,  fC[1], 68, wmma::mem_row_major);
    wmma::store_matrix_sync(sCh + ms * 72 + nb,      fE[0], 72, wmma::mem_row_major);
    wmma::store_matrix_sync(sCh + ms * 72 + nb + 16, fE[1], 72, wmma::mem_row_major);
    __syncthreads();
}

// ---------------- proj GEMM mainloop (BM=128) ----------------------------------
__device__ __forceinline__ void gemm128(
    const __half* __restrict__ Ah, const __half* __restrict__ Al,
    const __half* __restrict__ Bh, const __half* __restrict__ Bl,
    int m0, char* sm, float* sC, __half* sCh)
{
    const int tid = threadIdx.x;
    const int wid = tid >> 5;
    const int ms = (wid & 3) * 32;
    const int nb = (wid >> 2) * 32;
    const uint32_t sbase = smem_u32(sm);

    const int c0 = tid & 7;
    const uint32_t soA[4] = {
        (uint32_t)(((tid + 0)   >> 3) * ROWB + c0 * 16),
        (uint32_t)(((tid + 256) >> 3) * ROWB + c0 * 16),
        (uint32_t)(((tid + 512) >> 3) * ROWB + c0 * 16),
        (uint32_t)(((tid + 768) >> 3) * ROWB + c0 * 16)
    };
    const int rA[4] = { (tid + 0) >> 3, (tid + 256) >> 3,
                        (tid + 512) >> 3, (tid + 768) >> 3 };

    wmma::fragment<wmma::accumulator, 16, 16, 16, float> fC[2][2];
    wmma::fragment<wmma::accumulator, 16, 16, 16, __half> fE[2][2];
#pragma unroll
    for (int i = 0; i < 2; i++)
#pragma unroll
        for (int j = 0; j < 2; j++) {
            wmma::fill_fragment(fC[i][j], 0.0f);
            wmma::fill_fragment(fE[i][j], __float2half(0.0f));
        }

#pragma unroll
    for (int s = 0; s < 2; s++) {
        const int kt = s * KC;
        const uint32_t sb = sbase + (uint32_t)s * STG128;
#pragma unroll
        for (int v = 0; v < 4; v++) {
            const size_t ga = (size_t)(m0 + rA[v]) * H + kt + c0 * 8;
            cp16(sb + 0 * ARRB128 + soA[v], Ah + ga);
            cp16(sb + 1 * ARRB128 + soA[v], Al + ga);
        }
#pragma unroll
        for (int v = 0; v < 2; v++) {
            const size_t gb = (size_t)rA[v] * H + kt + c0 * 8;
            cp16(sb + 2 * ARRB128 + soA[v], Bh + gb);
            cp16(sb + 2 * ARRB128 + ARRB64 + soA[v], Bl + gb);
        }
        cp_commit();
    }

    for (int s = 0; s < NST; s++) {
        if (s < NST - 1) cp_wait1(); else cp_wait0();
        __syncthreads();

        const __half* st =
            reinterpret_cast<const __half*>(sm + (size_t)(s & 1) * STG128);
        const __half* sAh = st;
        const __half* sAl = st + ARRB128 / 2;
        const __half* sBh = st + 2 * (ARRB128 / 2);
        const __half* sBl = st + 2 * (ARRB128 / 2) + ARRB64 / 2;

#pragma unroll
        for (int ks = 0; ks < KC; ks += 16) {
            wmma::fragment<wmma::matrix_a, 16, 16, 16, __half,
                           wmma::row_major> fAh[2], fAl[2];
#pragma unroll
            for (int i = 0; i < 2; i++) {
                wmma::load_matrix_sync(fAh[i], sAh + (ms + i * 16) * PE + ks, PE);
                wmma::load_matrix_sync(fAl[i], sAl + (ms + i * 16) * PE + ks, PE);
            }
#pragma unroll
            for (int j = 0; j < 2; j++) {
                wmma::fragment<wmma::matrix_b, 16, 16, 16, __half,
                               wmma::col_major> fBh, fBl;
                const int nr = nb + j * 16;
                wmma::load_matrix_sync(fBh, sBh + nr * PE + ks, PE);
                wmma::load_matrix_sync(fBl, sBl + nr * PE + ks, PE);
#pragma unroll
                for (int i = 0; i < 2; i++) {
                    wmma::mma_sync(fC[i][j], fAh[i], fBh, fC[i][j]);
                    wmma::mma_sync(fE[i][j], fAh[i], fBl, fE[i][j]);
                    wmma::mma_sync(fE[i][j], fAl[i], fBh, fE[i][j]);
                }
            }
        }
        __syncthreads();

        if (s + 2 < NST) {
            const int kt = (s + 2) * KC;
            const uint32_t sb = sbase + (uint32_t)(s & 1) * STG128;
#pragma unroll
            for (int v = 0; v < 4; v++) {
                const size_t ga = (size_t)(m0 + rA[v]) * H + kt + c0 * 8;
                cp16(sb + 0 * ARRB128 + soA[v], Ah + ga);
                cp16(sb + 1 * ARRB128 + soA[v], Al + ga);
            }
#pragma unroll
            for (int v = 0; v < 2; v++) {
                const size_t gb = (size_t)rA[v] * H + kt + c0 * 8;
                cp16(sb + 2 * ARRB128 + soA[v], Bh + gb);
                cp16(sb + 2 * ARRB128 + ARRB64 + soA[v], Bl + gb);
            }
            cp_commit();
        }
    }

#pragma unroll
    for (int i = 0; i < 2; i++)
#pragma unroll
        for (int j = 0; j < 2; j++) {
            wmma::store_matrix_sync(sC + (ms + i * 16) * 68 + nb + j * 16,
                                    fC[i][j], 68, wmma::mem_row_major);
            wmma::store_matrix_sync(sCh + (ms + i * 16) * 72 + nb + j * 16,
                                    fE[i][j], 72, wmma::mem_row_major);
        }
    __syncthreads();
}

// ---------------- projection kernel (BM=128, occ 2) + partial argmax -----------
__global__ __launch_bounds__(256, 2)
void proj_tc(int useX0, float* __restrict__ dst, int t,
             const float* __restrict__ bias)
{
    extern __shared__ char sm[];
    float* sC  = reinterpret_cast<float*>(sm);
    __half* sCh = reinterpret_cast<__half*>(sm + 128 * 68 * 4);
    __shared__ float sBias[128];
    __shared__ float sPV[256];
    __shared__ int   sPI[256];

    const int tid = threadIdx.x;
    const int m0 = blockIdx.x * 128;
    if (tid < 128) sBias[tid] = bias[m0 + tid];

    const __half* Bh = useX0 ? g_xh : g_hh;
    const __half* Bl = useX0 ? g_xl : g_hl;
    gemm128(g_Wout_h, g_Wout_l, Bh, Bl, m0, sm, sC, sCh);

    const int ml = tid & 127;
    const int nlb = tid >> 7;
    const int gm = m0 + ml;
    const float bb = sBias[ml];
#pragma unroll
    for (int r = 0; r < 32; r++) {
        const int n = nlb + r * 2;
        dst[((size_t)n * T + t) * (size_t)V + gm] =
            sC[ml * 68 + n] + __half2float(sCh[ml * 72 + n]) + bb;
    }

    const int n = tid & 63, q = tid >> 6;
    float bv = -FLT_MAX;
    int bi = 0;
    for (int r = q * 32; r < q * 32 + 32; r++) {
        float v = sC[r * 68 + n] + __half2float(sCh[r * 72 + n]) + sBias[r];
        if (v > bv) { bv = v; bi = m0 + r; }
    }
    sPV[tid] = bv;
    sPI[tid] = bi;
    __syncthreads();
    if (tid < 64) {
        float v0 = sPV[tid];
        int   i0 = sPI[tid];
#pragma unroll
        for (int qq = 1; qq < 4; qq++) {
            float v = sPV[tid + qq * 64];
            int   i = sPI[tid + qq * 64];
            if (v > v0 || (v == v0 && i < i0)) { v0 = v; i0 = i; }
        }
        g_pv[blockIdx.x * B + tid] = v0;
        g_pi[blockIdx.x * B + tid] = i0;
    }
}

// ---------------- LSTM gates kernel (pass-parallel, BM=64, occ 2) --------------
__global__ __launch_bounds__(256, 2)
void lstm_tc()
{
    extern __shared__ char sm[];
    float* sC  = reinterpret_cast<float*>(sm);
    __half* sCh = reinterpret_cast<__half*>(sm + 64 * 68 * 4);
    const int pass = blockIdx.x >> 6;
    const int m0 = (blockIdx.x & 63) * 64;

    const __half* Ah = pass ? g_Whh_h : g_Wih_h;
    const __half* Al = pass ? g_Whh_l : g_Wih_l;
    const __half* Bh = pass ? g_hh : g_xh;
    const __half* Bl = pass ? g_hl : g_xl;
    gemm64(Ah, Al, Bh, Bl, m0, sm, sC, sCh);

    float* gp = pass ? g_gp1 : g_gp0;
    const int ml = threadIdx.x & 63;
    const int nlb = threadIdx.x >> 6;
    const int gm = m0 + ml;
#pragma unroll
    for (int r = 0; r < 16; r++) {
        const int n = nlb + r * 4;
        gp[(size_t)n * G4 + gm] = sC[ml * 68 + n] + __half2float(sCh[ml * 72 + n]);
    }
}

// ---------------- weight pre-split ---------------------------------------------
__global__ void split_weights(const float* __restrict__ src, int which, int n4) {
    int i4 = blockIdx.x * blockDim.x + threadIdx.x;
    if (i4 >= n4) return;
    __half* dh;
    __half* dl;
    if (which == 0)      { dh = g_Wout_h; dl = g_Wout_l; }
    else if (which == 1) { dh = g_Wih_h;  dl = g_Wih_l; }
    else                 { dh = g_Whh_h;  dl = g_Whh_l; }
    float4 v = reinterpret_cast<const float4*>(src)[i4];
    __half h0, l0, h1, l1, h2, l2, h3, l3;
    split_pair(v.x, h0, l0);
    split_pair(v.y, h1, l1);
    split_pair(v.z, h2, l2);
    split_pair(v.w, h3, l3);
    size_t o = (size_t)i4 * 4;
    dh[o] = h0; dh[o + 1] = h1; dh[o + 2] = h2; dh[o + 3] = h3;
    dl[o] = l0; dl[o + 1] = l1; dl[o + 2] = l2; dl[o + 3] = l3;
}

// ---------------- small kernels --------------------------------------------------
__global__ void init_kernel(const float* __restrict__ h0,
                            const float* __restrict__ c0,
                            const float* __restrict__ embed,
                            float* __restrict__ out, int mode) {
    int idx = blockIdx.x * blockDim.x + threadIdx.x;
    if (idx < B * H) {
        g_c[idx] = c0[idx];
        __half hi, lo;
        split_pair(h0[idx], hi, lo);
        g_hh[idx] = hi;
        g_hl[idx] = lo;
        split_pair(embed[(size_t)SOS * H + (idx & (H - 1))], hi, lo);
        g_xh[idx] = hi;
        g_xl[idx] = lo;
    }
    if (idx < B && mode)
        out[(size_t)B * T * V + (size_t)idx * T + 0] = (float)SOS;
}

__global__ void fill_zero(float* __restrict__ p, int n) {
    int i = blockIdx.x * blockDim.x + threadIdx.x;
    if (i < n) p[i] = 0.0f;
}

__global__ void lstm_act_kernel(const float* __restrict__ b_ih,
                                const float* __restrict__ b_hh) {
    int idx = blockIdx.x * blockDim.x + threadIdx.x;   // B*H
    int b = idx >> 10;
    int j = idx & (H - 1);
    const size_t base = (size_t)b * G4;
    float gi = g_gp0[base + j]        + g_gp1[base + j]        + b_ih[j]        + b_hh[j];
    float gf = g_gp0[base + j + 1024] + g_gp1[base + j + 1024] + b_ih[j + 1024] + b_hh[j + 1024];
    float gg = g_gp0[base + j + 2048] + g_gp1[base + j + 2048] + b_ih[j + 2048] + b_hh[j + 2048];
    float go = g_gp0[base + j + 3072] + g_gp1[base + j + 3072] + b_ih[j + 3072] + b_hh[j + 3072];
    float c  = g_c[idx];
    float si = 1.0f / (1.0f + expf(-gi));
    float sf = 1.0f / (1.0f + expf(-gf));
    float so = 1.0f / (1.0f + expf(-go));
    float c2 = sf * c + si * tanhf(gg);
    float h2 = so * tanhf(c2);
    g_c[idx] = c2;
    __half hi, lo;
    split_pair(h2, hi, lo);
    g_hh[idx] = hi;
    g_hl[idx] = lo;
}

// final argmax over proj partials + fused embed gather/split for next step
__global__ void argmax_final(float* __restrict__ out,
                             const float* __restrict__ embed,
                             int t, int mode) {
    const int b = blockIdx.x;
    const int tid = threadIdx.x;
    float bv = -FLT_MAX;
    int bi = 0x7fffffff;
    for (int i = tid; i < NPART; i += 256) {
        float v = g_pv[i * B + b];
        int   ix = g_pi[i * B + b];
        if (v > bv || (v == bv && ix < bi)) { bv = v; bi = ix; }
    }
    __shared__ float sv[256];
    __shared__ int   si[256];
    sv[tid] = bv;
    si[tid] = bi;
    __syncthreads();
    for (int s = 128; s > 0; s >>= 1) {
        if (tid < s) {
            float ov = sv[tid + s];
            int   oi = si[tid + s];
            if (ov > sv[tid] || (ov == sv[tid] && oi < si[tid])) {
                sv[tid] = ov;
                si[tid] = oi;
            }
        }
        __syncthreads();
    }
    const int sym = si[0];
    if (tid == 0 && mode)
        out[(size_t)B * T * V + (size_t)b * T + t] = (float)sym;
    const float4* erow = reinterpret_cast<const float4*>(embed + (size_t)sym * H);
    float4 v = erow[tid];
    int j = tid * 4;
    __half hi, lo;
    split_pair(v.x, hi, lo); g_xh[b * H + j]     = hi; g_xl[b * H + j]     = lo;
    split_pair(v.y, hi, lo); g_xh[b * H + j + 1] = hi; g_xl[b * H + j + 1] = lo;
    split_pair(v.z, hi, lo); g_xh[b * H + j + 2] = hi; g_xl[b * H + j + 2] = lo;
    split_pair(v.w, hi, lo); g_xh[b * H + j + 3] = hi; g_xl[b * H + j + 3] = lo;
}

// ---------------- launch ----------------------------------------------------------
extern "C" void kernel_launch(void* const* d_in, const int* in_sizes, int n_in,
                              void* d_out, int out_size) {
    const float* h0    = (const float*)d_in[1];
    const float* c0    = (const float*)d_in[2];
    const float* embed = (const float*)d_in[5];
    const float* w_ih  = (const float*)d_in[6];
    const float* w_hh  = (const float*)d_in[7];
    const float* b_ih  = (const float*)d_in[8];
    const float* b_hh  = (const float*)d_in[9];
    const float* w_out = (const float*)d_in[10];
    const float* b_out = (const float*)d_in[11];
    float* out = (float*)d_out;

    static int attr_done = 0;
    if (!attr_done) {
        cudaFuncSetAttribute(proj_tc, cudaFuncAttributeMaxDynamicSharedMemorySize, DSMEM_P);
        cudaFuncSetAttribute(lstm_tc, cudaFuncAttributeMaxDynamicSharedMemorySize, DSMEM_L);
        attr_done = 1;
    }

    const long long BTV = (long long)B * T * V;
    long long extra = (long long)out_size - BTV;
    int mode = (extra >= (long long)(B * T)) ? 1 : 0;

    init_kernel<<<(B * H + 511) / 512, 512>>>(h0, c0, embed, out, mode);

    split_weights<<<(V * H / 4 + 255) / 256, 256>>>(w_out, 0, V * H / 4);
    split_weights<<<(G4 * H / 4 + 255) / 256, 256>>>(w_ih, 1, G4 * H / 4);
    split_weights<<<(G4 * H / 4 + 255) / 256, 256>>>(w_hh, 2, G4 * H / 4);

    long long zstart = BTV + (mode ? (long long)(B * T) : 0);
    long long zcount = (long long)out_size - zstart;
    if (zcount > 0)
        fill_zero<<<(int)((zcount + 255) / 256), 256>>>(out + zstart, (int)zcount);

    proj_tc<<<V / 128, 256, DSMEM_P>>>(1, out, 0, b_out);

    for (int t = 1; t < T; t++) {
        lstm_tc<<<128, 256, DSMEM_L>>>();
        lstm_act_kernel<<<(B * H) / 256, 256>>>(b_ih, b_hh);
        proj_tc<<<V / 128, 256, DSMEM_P>>>(0, out, t, b_out);
        argmax_final<<<B, 256>>>(out, embed, t, mode);
    }
}